// round 14
// baseline (speedup 1.0000x reference)
#include <cuda_runtime.h>
#include <cuda_fp16.h>
#include <cstdint>

// ---------------- Problem constants ----------------
#define CB   4
#define CL   512
#define CD   1024
#define CED  2048
#define CNS  16
#define CRK  64
#define CKC  4
#define CML  (CB*CL)        // 2048
#define BLED (CB*CL*CED)    // 4194304

// ---------------- Scratch ----------------
__device__ __half g_xzh[CB*CL*2*CED];    // xz (half)
__device__ __half g_xch[2*BLED];         // conv+silu output (half)
__device__ float  g_dbc[2*CML*96];       // split-K accumulators (fp32)
__device__ __half g_dbch[2*CML*96];      // dbc as half
__device__ __half g_deltah[2*BLED];      // softplus(delta) (half)
__device__ __half g_yh[2*BLED];          // scan output (half)
__device__ __half g_ych[BLED];           // combined (half)
__device__ __half g_xh[CML*CD];          // x as half
__device__ __half g_wh[7077888];
#define OW_IN   0
#define OW_OUT  4194304
#define OWX_F   6291456
#define OWX_B   6488064
#define OWDT_F  6684672
#define OWDT_B  6815744

// ---------------- helpers ----------------
__device__ __forceinline__ float softplusf(float x) {
    return fmaxf(x, 0.f) + log1pf(__expf(-fabsf(x)));
}
__device__ __forceinline__ float siluf(float x) {
    return x / (1.f + __expf(-x));
}
__device__ __forceinline__ float ex2f(float x) {
    float y; asm("ex2.approx.ftz.f32 %0, %1;" : "=f"(y) : "f"(x));
    return y;
}
__device__ __forceinline__ void cp16(uint32_t dst, const void* src) {
    asm volatile("cp.async.cg.shared.global [%0], [%1], 16;" :: "r"(dst), "l"(src));
}
__device__ __forceinline__ void ldsm4(uint32_t& r0, uint32_t& r1, uint32_t& r2, uint32_t& r3, uint32_t addr) {
    asm volatile("ldmatrix.sync.aligned.m8n8.x4.shared.b16 {%0,%1,%2,%3}, [%4];"
                 : "=r"(r0), "=r"(r1), "=r"(r2), "=r"(r3) : "r"(addr));
}
__device__ __forceinline__ uint2 f4h(float4 v) {
    __half2 lo = __floats2half2_rn(v.x, v.y);
    __half2 hi = __floats2half2_rn(v.z, v.w);
    return make_uint2(*(uint32_t*)&lo, *(uint32_t*)&hi);
}
__device__ __forceinline__ float4 h4f(uint2 u) {
    float2 lo = __half22float2(*(__half2*)&u.x);
    float2 hi = __half22float2(*(__half2*)&u.y);
    return make_float4(lo.x, lo.y, hi.x, hi.y);
}
template<bool B> struct BC { static constexpr bool v = B; };

// ---------------- conversion kernels (split for stream overlap) ------------
// main: x (524288 f4) + W_in (1048576 f4)  — prerequisites of the xz GEMM
#define CVT_MAIN_TOTAL (524288+1048576)
__global__ void cvt_main_k(const float4* __restrict__ x, const float4* __restrict__ win,
                           uint2* __restrict__ xh, uint2* __restrict__ wh)
{
    int i = blockIdx.x * blockDim.x + threadIdx.x;
    if (i < 524288)  { xh[i] = f4h(x[i]); return; }                 i -= 524288;
    if (i < 1048576) wh[OW_IN/4 + i] = f4h(win[i]);
}
// rest: W_out | Wx | Wxb | Wdt | Wdtb | dbc-zero | out-zero
#define CVT_REST_TOTAL (524288+49152+49152+32768+32768+98304+524288)
__global__ void cvt_rest_k(const float4* __restrict__ wout,
                           const float4* __restrict__ wx,  const float4* __restrict__ wxb,
                           const float4* __restrict__ wdt, const float4* __restrict__ wdtb,
                           uint2* __restrict__ wh, float4* __restrict__ dbcz,
                           float4* __restrict__ outz)
{
    int i = blockIdx.x * blockDim.x + threadIdx.x;
    if (i < 524288)  { wh[OW_OUT/4 + i] = f4h(wout[i]); return; }   i -= 524288;
    if (i < 49152)   { wh[OWX_F/4  + i] = f4h(wx[i]);   return; }   i -= 49152;
    if (i < 49152)   { wh[OWX_B/4  + i] = f4h(wxb[i]);  return; }   i -= 49152;
    if (i < 32768)   { wh[OWDT_F/4 + i] = f4h(wdt[i]);  return; }   i -= 32768;
    if (i < 32768)   { wh[OWDT_B/4 + i] = f4h(wdtb[i]); return; }   i -= 32768;
    if (i < 98304)   { dbcz[i] = make_float4(0.f,0.f,0.f,0.f); return; } i -= 98304;
    if (i < 524288)  outz[i] = make_float4(0.f, 0.f, 0.f, 0.f);
}

__global__ void f2h_k(const float2* __restrict__ in, __half2* __restrict__ out, int n2) {
    int i = blockIdx.x * blockDim.x + threadIdx.x;
    if (i < n2) {
        float2 v = in[i];
        out[i] = __floats2half2_rn(v.x, v.y);
    }
}

#define LDKH 72
#define GNS  3

// ================= 8-warp FP16 GEMM (dbc / delta) =================
// DIRAX: 1 dir=blockIdx.x+dirofs (col0=0) + split-K on z (fp32 atomic);
//        2 dir=blockIdx.z+dirofs. OUTH: half output.
template<int BN, int EPI, int DIRAX, bool OUTH>
__global__ void __launch_bounds__(2*(BN/32)*32)
gemm_f16(const __half* __restrict__ A, int lda, size_t aStride,
         const __half* __restrict__ B0, const __half* __restrict__ B1, int ldb,
         void* __restrict__ Craw, int ldc, size_t cStride,
         int K, const float* __restrict__ bias0, const float* __restrict__ bias1,
         int dirofs)
{
    constexpr int BM = 128;
    constexpr int WARPS_N = BN/32;
    constexpr int THREADS = 2*WARPS_N*32;
    constexpr int STAGE_H = (BM+BN)*LDKH;
    extern __shared__ __half smh[];

    const int tid  = threadIdx.x;
    const int warp = tid >> 5, lane = tid & 31;
    const int wm = warp / WARPS_N, wn = warp % WARPS_N;
    const int g = lane >> 2, t = lane & 3;

    const int dir = (DIRAX==1) ? (blockIdx.x + dirofs) : (DIRAX==2 ? (blockIdx.z + dirofs) : 0);
    const int row0 = blockIdx.y * BM;
    const int col0 = (DIRAX==1) ? 0 : blockIdx.x * BN;
    const int nsplit = (DIRAX==1) ? gridDim.z : 1;
    const int Kc = K / nsplit;
    const int kbase = (DIRAX==1) ? blockIdx.z * Kc : 0;
    const int KT = Kc / 64;

    const __half* Aeff = A + (size_t)dir * aStride;
    const __half* Beff = dir ? B1 : B0;
    const float*  bias = dir ? bias1 : bias0;

    float acc[4][4][4];
#pragma unroll
    for (int i = 0; i < 4; i++)
#pragma unroll
        for (int j = 0; j < 4; j++)
#pragma unroll
            for (int q = 0; q < 4; q++) acc[i][j][q] = 0.f;

    const uint32_t smem0 = (uint32_t)__cvta_generic_to_shared(smh);
    const uint32_t aLane = (uint32_t)(((wm*64 + (lane & 7) + ((lane >> 3) & 1) * 8) * LDKH
                                     + (lane >> 4) * 8) * 2);
    const uint32_t bLane = (uint32_t)((BM*LDKH
                                     + (wn*32 + (lane & 7) + ((lane >> 4) & 1) * 8) * LDKH
                                     + ((lane >> 3) & 1) * 8) * 2);

    auto load_tile = [&](int kt, int s) {
        __half* As = smh + s*STAGE_H;
        __half* Bs = As + BM*LDKH;
        const int k0 = kbase + kt*64;
#pragma unroll 2
        for (int i = tid; i < BM*8; i += THREADS) {
            int m = i >> 3, kq = (i & 7) << 3;
            cp16((uint32_t)__cvta_generic_to_shared(As + m*LDKH + kq),
                 Aeff + (size_t)(row0+m)*lda + k0 + kq);
        }
#pragma unroll 2
        for (int i = tid; i < BN*8; i += THREADS) {
            int n = i >> 3, kq = (i & 7) << 3;
            cp16((uint32_t)__cvta_generic_to_shared(Bs + n*LDKH + kq),
                 Beff + (size_t)(col0+n)*ldb + k0 + kq);
        }
    };

    auto comp = [&](int s) {
        const uint32_t base = smem0 + (uint32_t)(s*STAGE_H)*2u;
#pragma unroll
        for (int ks = 0; ks < 4; ks++) {
            const uint32_t kb = (uint32_t)(ks*16)*2u;
            uint32_t a[4][4], b[2][4];
#pragma unroll
            for (int mt = 0; mt < 4; mt++)
                ldsm4(a[mt][0], a[mt][1], a[mt][2], a[mt][3],
                      base + aLane + (uint32_t)(mt*16*LDKH)*2u + kb);
#pragma unroll
            for (int np = 0; np < 2; np++)
                ldsm4(b[np][0], b[np][1], b[np][2], b[np][3],
                      base + bLane + (uint32_t)(np*16*LDKH)*2u + kb);
#pragma unroll
            for (int mt = 0; mt < 4; mt++)
#pragma unroll
                for (int nt = 0; nt < 4; nt++) {
                    const uint32_t bb0 = b[nt>>1][(nt&1)*2 + 0];
                    const uint32_t bb1 = b[nt>>1][(nt&1)*2 + 1];
                    asm volatile(
                        "mma.sync.aligned.m16n8k16.row.col.f32.f16.f16.f32 "
                        "{%0,%1,%2,%3}, {%4,%5,%6,%7}, {%8,%9}, {%0,%1,%2,%3};"
                        : "+f"(acc[mt][nt][0]), "+f"(acc[mt][nt][1]),
                          "+f"(acc[mt][nt][2]), "+f"(acc[mt][nt][3])
                        : "r"(a[mt][0]), "r"(a[mt][1]), "r"(a[mt][2]), "r"(a[mt][3]),
                          "r"(bb0), "r"(bb1));
                }
        }
    };

    load_tile(0, 0);
    asm volatile("cp.async.commit_group;");
    if (KT > 1) load_tile(1, 1);
    asm volatile("cp.async.commit_group;");

    for (int kt = 0; kt < KT; kt++) {
        asm volatile("cp.async.wait_group 1;");
        __syncthreads();
        if (kt + 2 < KT) load_tile(kt + 2, (kt + 2) % GNS);
        asm volatile("cp.async.commit_group;");
        comp(kt % GNS);
    }

    const bool use_atomic = (DIRAX == 1 && nsplit > 1);
#pragma unroll
    for (int mt = 0; mt < 4; mt++) {
        int row = row0 + wm*64 + mt*16 + g;
#pragma unroll
        for (int nt = 0; nt < 4; nt++) {
            int col = col0 + wn*32 + nt*8 + 2*t;
            float v0 = acc[mt][nt][0], v1 = acc[mt][nt][1];
            float v2 = acc[mt][nt][2], v3 = acc[mt][nt][3];
            if (EPI == 1) {
                v0 = softplusf(v0 + bias[col]);
                v1 = softplusf(v1 + bias[col+1]);
                v2 = softplusf(v2 + bias[col]);
                v3 = softplusf(v3 + bias[col+1]);
            }
            if (OUTH) {
                __half* Ceff = (__half*)Craw + (size_t)dir * cStride;
                *(__half2*)&Ceff[(size_t)row*ldc + col]     = __floats2half2_rn(v0, v1);
                *(__half2*)&Ceff[(size_t)(row+8)*ldc + col] = __floats2half2_rn(v2, v3);
            } else {
                float* Ceff = (float*)Craw + (size_t)dir * cStride;
                if (use_atomic) {
                    atomicAdd(&Ceff[(size_t)row*ldc + col],       v0);
                    atomicAdd(&Ceff[(size_t)row*ldc + col + 1],   v1);
                    atomicAdd(&Ceff[(size_t)(row+8)*ldc + col],   v2);
                    atomicAdd(&Ceff[(size_t)(row+8)*ldc + col+1], v3);
                } else {
                    *(float2*)&Ceff[(size_t)row*ldc + col]     = make_float2(v0, v1);
                    *(float2*)&Ceff[(size_t)(row+8)*ldc + col] = make_float2(v2, v3);
                }
            }
        }
    }
}

// ================= 16-warp FP16 GEMM (xz / out): warp tile 32x32 ===========
template<int DIRAX, bool OUTH>
__global__ void __launch_bounds__(512, 2)
gemm_f16w32(const __half* __restrict__ A, int lda,
            const __half* __restrict__ B, int ldb,
            void* __restrict__ Craw, int ldc, int K)
{
    constexpr int BM = 128, BN = 128, THREADS = 512;
    constexpr int STAGE_H = (BM+BN)*LDKH;
    extern __shared__ __half smh[];

    const int tid  = threadIdx.x;
    const int warp = tid >> 5, lane = tid & 31;
    const int wm = warp >> 2, wn = warp & 3;
    const int g = lane >> 2, t = lane & 3;

    const int row0 = blockIdx.y * BM;
    const int col0 = blockIdx.x * BN;
    const int nsplit = (DIRAX==3) ? gridDim.z : 1;
    const int Kc = K / nsplit;
    const int kbase = (DIRAX==3) ? blockIdx.z * Kc : 0;
    const int KT = Kc / 64;

    float acc[2][4][4];
#pragma unroll
    for (int i = 0; i < 2; i++)
#pragma unroll
        for (int j = 0; j < 4; j++)
#pragma unroll
            for (int q = 0; q < 4; q++) acc[i][j][q] = 0.f;

    const uint32_t smem0 = (uint32_t)__cvta_generic_to_shared(smh);
    const uint32_t aLane = (uint32_t)(((wm*32 + (lane & 7) + ((lane >> 3) & 1) * 8) * LDKH
                                     + (lane >> 4) * 8) * 2);
    const uint32_t bLane = (uint32_t)((BM*LDKH
                                     + (wn*32 + (lane & 7) + ((lane >> 4) & 1) * 8) * LDKH
                                     + ((lane >> 3) & 1) * 8) * 2);

    auto load_tile = [&](int kt, int s) {
        __half* As = smh + s*STAGE_H;
        __half* Bs = As + BM*LDKH;
        const int k0 = kbase + kt*64;
#pragma unroll 2
        for (int i = tid; i < BM*8; i += THREADS) {
            int m = i >> 3, kq = (i & 7) << 3;
            cp16((uint32_t)__cvta_generic_to_shared(As + m*LDKH + kq),
                 A + (size_t)(row0+m)*lda + k0 + kq);
        }
#pragma unroll 2
        for (int i = tid; i < BN*8; i += THREADS) {
            int n = i >> 3, kq = (i & 7) << 3;
            cp16((uint32_t)__cvta_generic_to_shared(Bs + n*LDKH + kq),
                 B + (size_t)(col0+n)*ldb + k0 + kq);
        }
    };

    auto comp = [&](int s) {
        const uint32_t base = smem0 + (uint32_t)(s*STAGE_H)*2u;
#pragma unroll
        for (int ks = 0; ks < 4; ks++) {
            const uint32_t kb = (uint32_t)(ks*16)*2u;
            uint32_t a[2][4], b[2][4];
#pragma unroll
            for (int mt = 0; mt < 2; mt++)
                ldsm4(a[mt][0], a[mt][1], a[mt][2], a[mt][3],
                      base + aLane + (uint32_t)(mt*16*LDKH)*2u + kb);
#pragma unroll
            for (int np = 0; np < 2; np++)
                ldsm4(b[np][0], b[np][1], b[np][2], b[np][3],
                      base + bLane + (uint32_t)(np*16*LDKH)*2u + kb);
#pragma unroll
            for (int mt = 0; mt < 2; mt++)
#pragma unroll
                for (int nt = 0; nt < 4; nt++) {
                    const uint32_t bb0 = b[nt>>1][(nt&1)*2 + 0];
                    const uint32_t bb1 = b[nt>>1][(nt&1)*2 + 1];
                    asm volatile(
                        "mma.sync.aligned.m16n8k16.row.col.f32.f16.f16.f32 "
                        "{%0,%1,%2,%3}, {%4,%5,%6,%7}, {%8,%9}, {%0,%1,%2,%3};"
                        : "+f"(acc[mt][nt][0]), "+f"(acc[mt][nt][1]),
                          "+f"(acc[mt][nt][2]), "+f"(acc[mt][nt][3])
                        : "r"(a[mt][0]), "r"(a[mt][1]), "r"(a[mt][2]), "r"(a[mt][3]),
                          "r"(bb0), "r"(bb1));
                }
        }
    };

    load_tile(0, 0);
    asm volatile("cp.async.commit_group;");
    if (KT > 1) load_tile(1, 1);
    asm volatile("cp.async.commit_group;");

    for (int kt = 0; kt < KT; kt++) {
        asm volatile("cp.async.wait_group 1;");
        __syncthreads();
        if (kt + 2 < KT) load_tile(kt + 2, (kt + 2) % GNS);
        asm volatile("cp.async.commit_group;");
        comp(kt % GNS);
    }

    const bool use_atomic = (DIRAX == 3 && nsplit > 1);
#pragma unroll
    for (int mt = 0; mt < 2; mt++) {
        int row = row0 + wm*32 + mt*16 + g;
#pragma unroll
        for (int nt = 0; nt < 4; nt++) {
            int col = col0 + wn*32 + nt*8 + 2*t;
            float v0 = acc[mt][nt][0], v1 = acc[mt][nt][1];
            float v2 = acc[mt][nt][2], v3 = acc[mt][nt][3];
            if (OUTH) {
                __half* C = (__half*)Craw;
                *(__half2*)&C[(size_t)row*ldc + col]     = __floats2half2_rn(v0, v1);
                *(__half2*)&C[(size_t)(row+8)*ldc + col] = __floats2half2_rn(v2, v3);
            } else {
                float* C = (float*)Craw;
                if (use_atomic) {
                    atomicAdd(&C[(size_t)row*ldc + col],       v0);
                    atomicAdd(&C[(size_t)row*ldc + col + 1],   v1);
                    atomicAdd(&C[(size_t)(row+8)*ldc + col],   v2);
                    atomicAdd(&C[(size_t)(row+8)*ldc + col+1], v3);
                } else {
                    *(float2*)&C[(size_t)row*ldc + col]     = make_float2(v0, v1);
                    *(float2*)&C[(size_t)(row+8)*ldc + col] = make_float2(v2, v3);
                }
            }
        }
    }
}

// ---------------- rolling-window conv + SiLU (half in, half out) -----------
__global__ void __launch_bounds__(256)
conv_silu_kernel(const uint2* __restrict__ xzh4,
                 const float4* __restrict__ cw0, const float4* __restrict__ cb0,
                 const float4* __restrict__ cw1, const float4* __restrict__ cb1,
                 uint2* __restrict__ xch, int dirofs)
{
    const int e4  = (blockIdx.x & 1) * 256 + threadIdx.x;
    const int tc  = blockIdx.x >> 1;
    const int b   = blockIdx.y;
    const int dir = blockIdx.z + dirofs;
    const int t0  = tc * 64;

    const float4* cw = dir ? cw1 : cw0;
    const float4 bi = (dir ? cb1 : cb0)[e4];
    const float4 w0 = cw[e4*4+0], w1 = cw[e4*4+1], w2 = cw[e4*4+2], w3 = cw[e4*4+3];

    auto ldx = [&](int ts) -> float4 {
        if (ts < 0) return make_float4(0.f, 0.f, 0.f, 0.f);
        int tg = dir ? (CL-1-ts) : ts;
        return h4f(xzh4[(size_t)((b << 9) + tg) * 1024 + e4]);
    };

    float4 p3 = ldx(t0-3), p2 = ldx(t0-2), p1 = ldx(t0-1);

    for (int tt = t0; tt < t0 + 64; tt++) {
        float4 cur = ldx(tt);
        float a0 = bi.x, a1 = bi.y, a2 = bi.z, a3 = bi.w;
        a0 = fmaf(w0.x, p3.x, a0); a0 = fmaf(w0.y, p2.x, a0);
        a0 = fmaf(w0.z, p1.x, a0); a0 = fmaf(w0.w, cur.x, a0);
        a1 = fmaf(w1.x, p3.y, a1); a1 = fmaf(w1.y, p2.y, a1);
        a1 = fmaf(w1.z, p1.y, a1); a1 = fmaf(w1.w, cur.y, a1);
        a2 = fmaf(w2.x, p3.z, a2); a2 = fmaf(w2.y, p2.z, a2);
        a2 = fmaf(w2.z, p1.z, a2); a2 = fmaf(w2.w, cur.z, a2);
        a3 = fmaf(w3.x, p3.w, a3); a3 = fmaf(w3.y, p2.w, a3);
        a3 = fmaf(w3.z, p1.w, a3); a3 = fmaf(w3.w, cur.w, a3);
        p3 = p2; p2 = p1; p1 = cur;
        __half2 lo = __floats2half2_rn(siluf(a0), siluf(a1));
        __half2 hi = __floats2half2_rn(siluf(a2), siluf(a3));
        xch[(dir << 20) + (b << 18) + (tt << 9) + e4] =
            make_uint2(*(uint32_t*)&lo, *(uint32_t*)&hi);
    }
}

// ---------------- selective scan (half inputs, half output) ----------------
#define SCAN_TC 16
__global__ void __launch_bounds__(128)
scan_kernel(const __half* __restrict__ delta,
            const __half* __restrict__ xc,
            const float* __restrict__ dbc,
            const __half* __restrict__ xz,
            const float* __restrict__ A_log_f, const float* __restrict__ A_log_b,
            const float* __restrict__ Dp_f,    const float* __restrict__ Dp_b,
            __half* __restrict__ y, int dirofs)
{
    __shared__ float sD[SCAN_TC][128];
    __shared__ float sX[SCAN_TC][128];
    __shared__ float sZ[SCAN_TC][128];
    __shared__ float sB[SCAN_TC][CNS];
    __shared__ float sC[SCAN_TC][CNS];

    const int e   = blockIdx.x * 128 + threadIdx.x;
    const int b   = blockIdx.y;
    const int dir = blockIdx.z + dirofs;
    const int tx  = threadIdx.x;

    const __half* dlt = delta + (size_t)dir * BLED;
    const __half* xcd = xc    + (size_t)dir * BLED;
    const float*  dbd = dbc   + (size_t)dir * CML * 96;
    __half*       yd  = y     + (size_t)dir * BLED;
    const float* A_log = dir ? A_log_b : A_log_f;
    const float* Dp    = dir ? Dp_b    : Dp_f;

    float Areg[CNS];
    bool fastok = true;
#pragma unroll
    for (int n = 0; n < CNS; n++) {
        float a = -__expf(A_log[e*CNS + n]);
        Areg[n] = a * 1.4426950408889634f;
        fastok = fastok && (fabsf(a + (float)(n+1)) < 1e-3f * (float)(n+1));
    }
    const bool fastA = __syncthreads_and(fastok);
    const float Dpe = Dp[e];

    float h[CNS];
#pragma unroll
    for (int n = 0; n < CNS; n++) h[n] = 0.f;

    auto run = [&](auto FC) {
        constexpr bool FAST = decltype(FC)::v;
        for (int t0 = 0; t0 < CL; t0 += SCAN_TC) {
            __syncthreads();
#pragma unroll
            for (int it = 0; it < SCAN_TC; it++) {
                int t = t0 + it;
                size_t r = (size_t)(b*CL + t) * CED + e;
                sD[it][tx] = __half2float(dlt[r]);
                sX[it][tx] = __half2float(xcd[r]);
                int tz = dir ? (CL-1-t) : t;
                sZ[it][tx] = __half2float(xz[((size_t)(b*CL + tz) << 12) + CED + e]);
            }
            for (int j = tx; j < SCAN_TC*CNS; j += 128) {
                int it = j >> 4, n = j & (CNS-1);
                size_t r = (size_t)(b*CL + t0 + it) * 96;
                sB[it][n] = dbd[r + CRK + n];
                sC[it][n] = dbd[r + CRK + CNS + n];
            }
            __syncthreads();

#pragma unroll
            for (int it = 0; it < SCAN_TC; it++) {
                float d  = sD[it][tx];
                float xv = sX[it][tx];
                float dx = d * xv;
                float dA[CNS];
                if (FAST) {
                    float r1 = ex2f(-1.4426950408889634f * d);   // exp(-d)
                    float r2 = r1*r1, r3 = r2*r1, r4 = r2*r2;
                    float r8 = r4*r4, r12 = r8*r4;
                    dA[0]=r1;      dA[1]=r2;      dA[2]=r3;      dA[3]=r4;
                    dA[4]=r4*r1;   dA[5]=r4*r2;   dA[6]=r4*r3;   dA[7]=r8;
                    dA[8]=r8*r1;   dA[9]=r8*r2;   dA[10]=r8*r3;  dA[11]=r8*r4;
                    dA[12]=r12*r1; dA[13]=r12*r2; dA[14]=r12*r3; dA[15]=r8*r8;
                } else {
#pragma unroll
                    for (int n = 0; n < CNS; n++) dA[n] = ex2f(d * Areg[n]);
                }
                float y0 = 0.f, y1 = 0.f, y2 = 0.f, y3 = 0.f;
#pragma unroll
                for (int n = 0; n < CNS; n += 4) {
                    h[n+0] = fmaf(dA[n+0], h[n+0], dx * sB[it][n+0]);
                    h[n+1] = fmaf(dA[n+1], h[n+1], dx * sB[it][n+1]);
                    h[n+2] = fmaf(dA[n+2], h[n+2], dx * sB[it][n+2]);
                    h[n+3] = fmaf(dA[n+3], h[n+3], dx * sB[it][n+3]);
                    y0 = fmaf(h[n+0], sC[it][n+0], y0);
                    y1 = fmaf(h[n+1], sC[it][n+1], y1);
                    y2 = fmaf(h[n+2], sC[it][n+2], y2);
                    y3 = fmaf(h[n+3], sC[it][n+3], y3);
                }
                float zv = sZ[it][tx];
                float yo = ((y0+y1) + (y2+y3)) + Dpe * xv;
                yd[(size_t)(b*CL + t0 + it)*CED + e] = __float2half_rn(yo * siluf(zv));
            }
        }
    };
    if (fastA) run(BC<true>{});
    else       run(BC<false>{});
}

// ---------------- combine (half2 in, half2 out) ------------------
__global__ void combine_kernel(const __half2* __restrict__ y0,
                               const __half2* __restrict__ y1,
                               __half2* __restrict__ yc)
{
    int idx = blockIdx.x * blockDim.x + threadIdx.x;
    int e2 = idx & (CED/2 - 1);
    int t  = (idx >> 10) & (CL-1);
    int b  = idx >> 19;
    float2 a  = __half22float2(y0[idx]);
    float2 bb = __half22float2(y1[(size_t)(b*CL + (CL-1-t))*(CED/2) + e2]);
    yc[idx] = __floats2half2_rn(0.5f*(a.x + bb.x), 0.5f*(a.y + bb.y));
}

// ---------------- launch ----------------
extern "C" void kernel_launch(void* const* d_in, const int* in_sizes, int n_in,
                              void* d_out, int out_size)
{
    const float* x      = (const float*)d_in[0];
    const float* W_in   = (const float*)d_in[1];
    const float* conv_w = (const float*)d_in[2];
    const float* conv_b = (const float*)d_in[3];
    const float* Wx     = (const float*)d_in[4];
    const float* Wdt    = (const float*)d_in[5];
    const float* b_dt   = (const float*)d_in[6];
    const float* A_log  = (const float*)d_in[7];
    const float* Dp     = (const float*)d_in[8];
    const float* conv_w_b = (const float*)d_in[9];
    const float* conv_b_b = (const float*)d_in[10];
    const float* Wx_b   = (const float*)d_in[11];
    const float* Wdt_b  = (const float*)d_in[12];
    const float* b_dt_b = (const float*)d_in[13];
    const float* A_log_b= (const float*)d_in[14];
    const float* Dp_b   = (const float*)d_in[15];
    const float* W_out  = (const float*)d_in[16];
    float* out = (float*)d_out;

    float *p_dbc;
    __half *p_xzh, *p_xch, *p_dbch, *p_deltah, *p_yh, *p_ych, *p_xh, *p_wh;
    cudaGetSymbolAddress((void**)&p_xzh,    g_xzh);
    cudaGetSymbolAddress((void**)&p_xch,    g_xch);
    cudaGetSymbolAddress((void**)&p_dbc,    g_dbc);
    cudaGetSymbolAddress((void**)&p_dbch,   g_dbch);
    cudaGetSymbolAddress((void**)&p_deltah, g_deltah);
    cudaGetSymbolAddress((void**)&p_yh,     g_yh);
    cudaGetSymbolAddress((void**)&p_ych,    g_ych);
    cudaGetSymbolAddress((void**)&p_xh,     g_xh);
    cudaGetSymbolAddress((void**)&p_wh,     g_wh);

    constexpr int SMEM128 = GNS*(128+128)*LDKH*2;   // 110592
    constexpr int SMEM96  = GNS*(128+96) *LDKH*2;   //  96768
    cudaFuncSetAttribute(gemm_f16w32<0,true>,    cudaFuncAttributeMaxDynamicSharedMemorySize, SMEM128);
    cudaFuncSetAttribute(gemm_f16w32<3,false>,   cudaFuncAttributeMaxDynamicSharedMemorySize, SMEM128);
    cudaFuncSetAttribute(gemm_f16<128,1,2,true>, cudaFuncAttributeMaxDynamicSharedMemorySize, SMEM128);
    cudaFuncSetAttribute(gemm_f16<96,0,1,false>, cudaFuncAttributeMaxDynamicSharedMemorySize, SMEM96);

    // lazy-init side stream + fork/join events (no device allocations)
    static cudaStream_t s1 = nullptr;
    static cudaEvent_t  e0 = nullptr, e1 = nullptr, e2 = nullptr, e3 = nullptr;
    if (!s1) {
        cudaStreamCreateWithFlags(&s1, cudaStreamNonBlocking);
        cudaEventCreateWithFlags(&e0, cudaEventDisableTiming);
        cudaEventCreateWithFlags(&e1, cudaEventDisableTiming);
        cudaEventCreateWithFlags(&e2, cudaEventDisableTiming);
        cudaEventCreateWithFlags(&e3, cudaEventDisableTiming);
    }

    // ---- stream 0: prerequisites of xz GEMM ----
    cvt_main_k<<<(CVT_MAIN_TOTAL + 255)/256, 256>>>(
        (const float4*)x, (const float4*)W_in, (uint2*)p_xh, (uint2*)p_wh);
    cudaEventRecord(e0, 0);

    // ---- fork: s1 converts remaining weights + zeros while xz GEMM runs ----
    cudaStreamWaitEvent(s1, e0, 0);
    cvt_rest_k<<<(CVT_REST_TOTAL + 255)/256, 256, 0, s1>>>(
        (const float4*)W_out, (const float4*)Wx, (const float4*)Wx_b,
        (const float4*)Wdt, (const float4*)Wdt_b,
        (uint2*)p_wh, (float4*)p_dbc, (float4*)out);
    cudaEventRecord(e1, s1);

    // ---- stream 0: xz GEMM + forward chain ----
    gemm_f16w32<0,true><<<dim3(32,16,1), 512, SMEM128>>>(
        p_xh, CD, p_wh+OW_IN, CD, p_xzh, 2*CED, CD);

    conv_silu_kernel<<<dim3(16, CB, 1), 256>>>(
        (const uint2*)p_xzh, (const float4*)conv_w, (const float4*)conv_b,
        (const float4*)conv_w_b, (const float4*)conv_b_b, (uint2*)p_xch, 0);
    cudaEventRecord(e2, 0);            // xz ready (conv(f) queued after xz)

    cudaStreamWaitEvent(0, e1, 0);     // Wx halves + zeros ready before dbc(f)
    gemm_f16<96,0,1,false><<<dim3(1,16,8), 192, SMEM96, 0>>>(
        p_xch, CED, (size_t)BLED, p_wh+OWX_F, p_wh+OWX_B, CED,
        p_dbc, 96, (size_t)CML*96, CED, nullptr, nullptr, 0);
    f2h_k<<<(CML*96/2 + 255)/256, 256>>>(
        (const float2*)p_dbc, (__half2*)p_dbch, CML*96/2);
    gemm_f16<128,1,2,true><<<dim3(16,16,1), 256, SMEM128, 0>>>(
        p_dbch, 96, (size_t)CML*96, p_wh+OWDT_F, p_wh+OWDT_B, CRK,
        p_deltah, CED, (size_t)BLED, CRK, b_dt, b_dt_b, 0);
    scan_kernel<<<dim3(CED/128, CB, 1), 128>>>(
        p_deltah, p_xch, p_dbc, p_xzh, A_log, A_log_b, Dp, Dp_b, p_yh, 0);

    // ---- s1: backward chain (waits for xz via e2; cvt_rest precedes on s1) ----
    cudaStreamWaitEvent(s1, e2, 0);
    conv_silu_kernel<<<dim3(16, CB, 1), 256, 0, s1>>>(
        (const uint2*)p_xzh, (const float4*)conv_w, (const float4*)conv_b,
        (const float4*)conv_w_b, (const float4*)conv_b_b, (uint2*)p_xch, 1);
    gemm_f16<96,0,1,false><<<dim3(1,16,8), 192, SMEM96, s1>>>(
        p_xch, CED, (size_t)BLED, p_wh+OWX_F, p_wh+OWX_B, CED,
        p_dbc, 96, (size_t)CML*96, CED, nullptr, nullptr, 1);
    f2h_k<<<(CML*96/2 + 255)/256, 256, 0, s1>>>(
        (const float2*)(p_dbc + CML*96), (__half2*)(p_dbch + CML*96), CML*96/2);
    gemm_f16<128,1,2,true><<<dim3(16,16,1), 256, SMEM128, s1>>>(
        p_dbch, 96, (size_t)CML*96, p_wh+OWDT_F, p_wh+OWDT_B, CRK,
        p_deltah, CED, (size_t)BLED, CRK, b_dt, b_dt_b, 1);
    scan_kernel<<<dim3(CED/128, CB, 1), 128, 0, s1>>>(
        p_deltah, p_xch, p_dbc, p_xzh, A_log, A_log_b, Dp, Dp_b, p_yh, 1);
    cudaEventRecord(e3, s1);

    // ---- join + epilogue on stream 0 ----
    cudaStreamWaitEvent(0, e3, 0);
    combine_kernel<<<(BLED/2)/256, 256>>>(
        (const __half2*)p_yh, (const __half2*)(p_yh + BLED), (__half2*)p_ych);
    gemm_f16w32<3,false><<<dim3(8,16,2), 512, SMEM128>>>(
        p_ych, CED, p_wh+OW_OUT, CED, out, CD, CED);
}

// round 15
// speedup vs baseline: 1.1964x; 1.1964x over previous
#include <cuda_runtime.h>
#include <cuda_fp16.h>
#include <cstdint>

// ---------------- Problem constants ----------------
#define CB   4
#define CL   512
#define CD   1024
#define CED  2048
#define CNS  16
#define CRK  64
#define CKC  4
#define CML  (CB*CL)        // 2048
#define BLED (CB*CL*CED)    // 4194304

// ---------------- Scratch ----------------
__device__ __half g_xzh[CB*CL*2*CED];    // xz (half)
__device__ __half g_xch[2*BLED];         // conv+silu output (half)
__device__ float  g_dbc[2*CML*96];       // split-K accumulators (fp32)
__device__ __half g_dbch[2*CML*96];      // dbc as half
__device__ __half g_deltah[2*BLED];      // softplus(delta) (half)
__device__ __half g_yh[2*BLED];          // scan output (half)
__device__ __half g_ych[BLED];           // combined (half)
__device__ __half g_xh[CML*CD];          // x as half
__device__ __half g_wh[7077888];
#define OW_IN   0
#define OW_OUT  4194304
#define OWX_F   6291456
#define OWX_B   6488064
#define OWDT_F  6684672
#define OWDT_B  6815744

// ---------------- helpers ----------------
__device__ __forceinline__ float softplusf(float x) {
    return fmaxf(x, 0.f) + log1pf(__expf(-fabsf(x)));
}
__device__ __forceinline__ float siluf(float x) {
    return x / (1.f + __expf(-x));
}
__device__ __forceinline__ float ex2f(float x) {
    float y; asm("ex2.approx.ftz.f32 %0, %1;" : "=f"(y) : "f"(x));
    return y;
}
__device__ __forceinline__ void cp16(uint32_t dst, const void* src) {
    asm volatile("cp.async.cg.shared.global [%0], [%1], 16;" :: "r"(dst), "l"(src));
}
__device__ __forceinline__ void ldsm4(uint32_t& r0, uint32_t& r1, uint32_t& r2, uint32_t& r3, uint32_t addr) {
    asm volatile("ldmatrix.sync.aligned.m8n8.x4.shared.b16 {%0,%1,%2,%3}, [%4];"
                 : "=r"(r0), "=r"(r1), "=r"(r2), "=r"(r3) : "r"(addr));
}
__device__ __forceinline__ uint2 f4h(float4 v) {
    __half2 lo = __floats2half2_rn(v.x, v.y);
    __half2 hi = __floats2half2_rn(v.z, v.w);
    return make_uint2(*(uint32_t*)&lo, *(uint32_t*)&hi);
}
__device__ __forceinline__ float4 h4f(uint2 u) {
    float2 lo = __half22float2(*(__half2*)&u.x);
    float2 hi = __half22float2(*(__half2*)&u.y);
    return make_float4(lo.x, lo.y, hi.x, hi.y);
}
template<bool B> struct BC { static constexpr bool v = B; };

// ---------------- merged conversion + zero ----------------
#define CVT_TOTAL (524288+1048576+524288+49152+49152+32768+32768+98304+524288)
__global__ void cvt_all_k(const float4* __restrict__ x,
                          const float4* __restrict__ win,  const float4* __restrict__ wout,
                          const float4* __restrict__ wx,   const float4* __restrict__ wxb,
                          const float4* __restrict__ wdt,  const float4* __restrict__ wdtb,
                          uint2* __restrict__ xh, uint2* __restrict__ wh,
                          float4* __restrict__ dbcz, float4* __restrict__ outz)
{
    int i = blockIdx.x * blockDim.x + threadIdx.x;
    if (i < 524288)  { xh[i] = f4h(x[i]); return; }                 i -= 524288;
    if (i < 1048576) { wh[OW_IN/4  + i] = f4h(win[i]);  return; }   i -= 1048576;
    if (i < 524288)  { wh[OW_OUT/4 + i] = f4h(wout[i]); return; }   i -= 524288;
    if (i < 49152)   { wh[OWX_F/4  + i] = f4h(wx[i]);   return; }   i -= 49152;
    if (i < 49152)   { wh[OWX_B/4  + i] = f4h(wxb[i]);  return; }   i -= 49152;
    if (i < 32768)   { wh[OWDT_F/4 + i] = f4h(wdt[i]);  return; }   i -= 32768;
    if (i < 32768)   { wh[OWDT_B/4 + i] = f4h(wdtb[i]); return; }   i -= 32768;
    if (i < 98304)   { dbcz[i] = make_float4(0.f,0.f,0.f,0.f); return; } i -= 98304;
    if (i < 524288)  outz[i] = make_float4(0.f, 0.f, 0.f, 0.f);
}

__global__ void f2h_k(const float2* __restrict__ in, __half2* __restrict__ out, int n2) {
    int i = blockIdx.x * blockDim.x + threadIdx.x;
    if (i < n2) {
        float2 v = in[i];
        out[i] = __floats2half2_rn(v.x, v.y);
    }
}

#define LDKH 72
#define GNS  3

// ================= 8-warp FP16 GEMM (dbc / delta) =================
template<int BN, int EPI, int DIRAX, bool OUTH>
__global__ void __launch_bounds__(2*(BN/32)*32)
gemm_f16(const __half* __restrict__ A, int lda, size_t aStride,
         const __half* __restrict__ B0, const __half* __restrict__ B1, int ldb,
         void* __restrict__ Craw, int ldc, size_t cStride,
         int K, const float* __restrict__ bias0, const float* __restrict__ bias1)
{
    constexpr int BM = 128;
    constexpr int WARPS_N = BN/32;
    constexpr int THREADS = 2*WARPS_N*32;
    constexpr int STAGE_H = (BM+BN)*LDKH;
    extern __shared__ __half smh[];

    const int tid  = threadIdx.x;
    const int warp = tid >> 5, lane = tid & 31;
    const int wm = warp / WARPS_N, wn = warp % WARPS_N;
    const int g = lane >> 2, t = lane & 3;

    const int dir = (DIRAX==1) ? blockIdx.x : (DIRAX==2 ? blockIdx.z : 0);
    const int row0 = blockIdx.y * BM;
    const int col0 = (DIRAX==1) ? 0 : blockIdx.x * BN;
    const int nsplit = (DIRAX==1) ? gridDim.z : 1;
    const int Kc = K / nsplit;
    const int kbase = (DIRAX==1) ? blockIdx.z * Kc : 0;
    const int KT = Kc / 64;

    const __half* Aeff = A + (size_t)dir * aStride;
    const __half* Beff = dir ? B1 : B0;
    const float*  bias = dir ? bias1 : bias0;

    float acc[4][4][4];
#pragma unroll
    for (int i = 0; i < 4; i++)
#pragma unroll
        for (int j = 0; j < 4; j++)
#pragma unroll
            for (int q = 0; q < 4; q++) acc[i][j][q] = 0.f;

    const uint32_t smem0 = (uint32_t)__cvta_generic_to_shared(smh);
    const uint32_t aLane = (uint32_t)(((wm*64 + (lane & 7) + ((lane >> 3) & 1) * 8) * LDKH
                                     + (lane >> 4) * 8) * 2);
    const uint32_t bLane = (uint32_t)((BM*LDKH
                                     + (wn*32 + (lane & 7) + ((lane >> 4) & 1) * 8) * LDKH
                                     + ((lane >> 3) & 1) * 8) * 2);

    auto load_tile = [&](int kt, int s) {
        __half* As = smh + s*STAGE_H;
        __half* Bs = As + BM*LDKH;
        const int k0 = kbase + kt*64;
#pragma unroll 2
        for (int i = tid; i < BM*8; i += THREADS) {
            int m = i >> 3, kq = (i & 7) << 3;
            cp16((uint32_t)__cvta_generic_to_shared(As + m*LDKH + kq),
                 Aeff + (size_t)(row0+m)*lda + k0 + kq);
        }
#pragma unroll 2
        for (int i = tid; i < BN*8; i += THREADS) {
            int n = i >> 3, kq = (i & 7) << 3;
            cp16((uint32_t)__cvta_generic_to_shared(Bs + n*LDKH + kq),
                 Beff + (size_t)(col0+n)*ldb + k0 + kq);
        }
    };

    auto comp = [&](int s) {
        const uint32_t base = smem0 + (uint32_t)(s*STAGE_H)*2u;
#pragma unroll
        for (int ks = 0; ks < 4; ks++) {
            const uint32_t kb = (uint32_t)(ks*16)*2u;
            uint32_t a[4][4], b[2][4];
#pragma unroll
            for (int mt = 0; mt < 4; mt++)
                ldsm4(a[mt][0], a[mt][1], a[mt][2], a[mt][3],
                      base + aLane + (uint32_t)(mt*16*LDKH)*2u + kb);
#pragma unroll
            for (int np = 0; np < 2; np++)
                ldsm4(b[np][0], b[np][1], b[np][2], b[np][3],
                      base + bLane + (uint32_t)(np*16*LDKH)*2u + kb);
#pragma unroll
            for (int mt = 0; mt < 4; mt++)
#pragma unroll
                for (int nt = 0; nt < 4; nt++) {
                    const uint32_t bb0 = b[nt>>1][(nt&1)*2 + 0];
                    const uint32_t bb1 = b[nt>>1][(nt&1)*2 + 1];
                    asm volatile(
                        "mma.sync.aligned.m16n8k16.row.col.f32.f16.f16.f32 "
                        "{%0,%1,%2,%3}, {%4,%5,%6,%7}, {%8,%9}, {%0,%1,%2,%3};"
                        : "+f"(acc[mt][nt][0]), "+f"(acc[mt][nt][1]),
                          "+f"(acc[mt][nt][2]), "+f"(acc[mt][nt][3])
                        : "r"(a[mt][0]), "r"(a[mt][1]), "r"(a[mt][2]), "r"(a[mt][3]),
                          "r"(bb0), "r"(bb1));
                }
        }
    };

    load_tile(0, 0);
    asm volatile("cp.async.commit_group;");
    if (KT > 1) load_tile(1, 1);
    asm volatile("cp.async.commit_group;");

    for (int kt = 0; kt < KT; kt++) {
        asm volatile("cp.async.wait_group 1;");
        __syncthreads();
        if (kt + 2 < KT) load_tile(kt + 2, (kt + 2) % GNS);
        asm volatile("cp.async.commit_group;");
        comp(kt % GNS);
    }

    const bool use_atomic = (DIRAX == 1 && nsplit > 1);
#pragma unroll
    for (int mt = 0; mt < 4; mt++) {
        int row = row0 + wm*64 + mt*16 + g;
#pragma unroll
        for (int nt = 0; nt < 4; nt++) {
            int col = col0 + wn*32 + nt*8 + 2*t;
            float v0 = acc[mt][nt][0], v1 = acc[mt][nt][1];
            float v2 = acc[mt][nt][2], v3 = acc[mt][nt][3];
            if (EPI == 1) {
                v0 = softplusf(v0 + bias[col]);
                v1 = softplusf(v1 + bias[col+1]);
                v2 = softplusf(v2 + bias[col]);
                v3 = softplusf(v3 + bias[col+1]);
            }
            if (OUTH) {
                __half* Ceff = (__half*)Craw + (size_t)dir * cStride;
                *(__half2*)&Ceff[(size_t)row*ldc + col]     = __floats2half2_rn(v0, v1);
                *(__half2*)&Ceff[(size_t)(row+8)*ldc + col] = __floats2half2_rn(v2, v3);
            } else {
                float* Ceff = (float*)Craw + (size_t)dir * cStride;
                if (use_atomic) {
                    atomicAdd(&Ceff[(size_t)row*ldc + col],       v0);
                    atomicAdd(&Ceff[(size_t)row*ldc + col + 1],   v1);
                    atomicAdd(&Ceff[(size_t)(row+8)*ldc + col],   v2);
                    atomicAdd(&Ceff[(size_t)(row+8)*ldc + col+1], v3);
                } else {
                    *(float2*)&Ceff[(size_t)row*ldc + col]     = make_float2(v0, v1);
                    *(float2*)&Ceff[(size_t)(row+8)*ldc + col] = make_float2(v2, v3);
                }
            }
        }
    }
}

// ================= 16-warp FP16 GEMM (xz / out): warp tile 32x32 ===========
template<int DIRAX, bool OUTH>
__global__ void __launch_bounds__(512, 2)
gemm_f16w32(const __half* __restrict__ A, int lda,
            const __half* __restrict__ B, int ldb,
            void* __restrict__ Craw, int ldc, int K)
{
    constexpr int BM = 128, BN = 128, THREADS = 512;
    constexpr int STAGE_H = (BM+BN)*LDKH;
    extern __shared__ __half smh[];

    const int tid  = threadIdx.x;
    const int warp = tid >> 5, lane = tid & 31;
    const int wm = warp >> 2, wn = warp & 3;
    const int g = lane >> 2, t = lane & 3;

    const int row0 = blockIdx.y * BM;
    const int col0 = blockIdx.x * BN;
    const int nsplit = (DIRAX==3) ? gridDim.z : 1;
    const int Kc = K / nsplit;
    const int kbase = (DIRAX==3) ? blockIdx.z * Kc : 0;
    const int KT = Kc / 64;

    float acc[2][4][4];
#pragma unroll
    for (int i = 0; i < 2; i++)
#pragma unroll
        for (int j = 0; j < 4; j++)
#pragma unroll
            for (int q = 0; q < 4; q++) acc[i][j][q] = 0.f;

    const uint32_t smem0 = (uint32_t)__cvta_generic_to_shared(smh);
    const uint32_t aLane = (uint32_t)(((wm*32 + (lane & 7) + ((lane >> 3) & 1) * 8) * LDKH
                                     + (lane >> 4) * 8) * 2);
    const uint32_t bLane = (uint32_t)((BM*LDKH
                                     + (wn*32 + (lane & 7) + ((lane >> 4) & 1) * 8) * LDKH
                                     + ((lane >> 3) & 1) * 8) * 2);

    auto load_tile = [&](int kt, int s) {
        __half* As = smh + s*STAGE_H;
        __half* Bs = As + BM*LDKH;
        const int k0 = kbase + kt*64;
#pragma unroll 2
        for (int i = tid; i < BM*8; i += THREADS) {
            int m = i >> 3, kq = (i & 7) << 3;
            cp16((uint32_t)__cvta_generic_to_shared(As + m*LDKH + kq),
                 A + (size_t)(row0+m)*lda + k0 + kq);
        }
#pragma unroll 2
        for (int i = tid; i < BN*8; i += THREADS) {
            int n = i >> 3, kq = (i & 7) << 3;
            cp16((uint32_t)__cvta_generic_to_shared(Bs + n*LDKH + kq),
                 B + (size_t)(col0+n)*ldb + k0 + kq);
        }
    };

    auto comp = [&](int s) {
        const uint32_t base = smem0 + (uint32_t)(s*STAGE_H)*2u;
#pragma unroll
        for (int ks = 0; ks < 4; ks++) {
            const uint32_t kb = (uint32_t)(ks*16)*2u;
            uint32_t a[2][4], b[2][4];
#pragma unroll
            for (int mt = 0; mt < 2; mt++)
                ldsm4(a[mt][0], a[mt][1], a[mt][2], a[mt][3],
                      base + aLane + (uint32_t)(mt*16*LDKH)*2u + kb);
#pragma unroll
            for (int np = 0; np < 2; np++)
                ldsm4(b[np][0], b[np][1], b[np][2], b[np][3],
                      base + bLane + (uint32_t)(np*16*LDKH)*2u + kb);
#pragma unroll
            for (int mt = 0; mt < 2; mt++)
#pragma unroll
                for (int nt = 0; nt < 4; nt++) {
                    const uint32_t bb0 = b[nt>>1][(nt&1)*2 + 0];
                    const uint32_t bb1 = b[nt>>1][(nt&1)*2 + 1];
                    asm volatile(
                        "mma.sync.aligned.m16n8k16.row.col.f32.f16.f16.f32 "
                        "{%0,%1,%2,%3}, {%4,%5,%6,%7}, {%8,%9}, {%0,%1,%2,%3};"
                        : "+f"(acc[mt][nt][0]), "+f"(acc[mt][nt][1]),
                          "+f"(acc[mt][nt][2]), "+f"(acc[mt][nt][3])
                        : "r"(a[mt][0]), "r"(a[mt][1]), "r"(a[mt][2]), "r"(a[mt][3]),
                          "r"(bb0), "r"(bb1));
                }
        }
    };

    load_tile(0, 0);
    asm volatile("cp.async.commit_group;");
    if (KT > 1) load_tile(1, 1);
    asm volatile("cp.async.commit_group;");

    for (int kt = 0; kt < KT; kt++) {
        asm volatile("cp.async.wait_group 1;");
        __syncthreads();
        if (kt + 2 < KT) load_tile(kt + 2, (kt + 2) % GNS);
        asm volatile("cp.async.commit_group;");
        comp(kt % GNS);
    }

    const bool use_atomic = (DIRAX == 3 && nsplit > 1);
#pragma unroll
    for (int mt = 0; mt < 2; mt++) {
        int row = row0 + wm*32 + mt*16 + g;
#pragma unroll
        for (int nt = 0; nt < 4; nt++) {
            int col = col0 + wn*32 + nt*8 + 2*t;
            float v0 = acc[mt][nt][0], v1 = acc[mt][nt][1];
            float v2 = acc[mt][nt][2], v3 = acc[mt][nt][3];
            if (OUTH) {
                __half* C = (__half*)Craw;
                *(__half2*)&C[(size_t)row*ldc + col]     = __floats2half2_rn(v0, v1);
                *(__half2*)&C[(size_t)(row+8)*ldc + col] = __floats2half2_rn(v2, v3);
            } else {
                float* C = (float*)Craw;
                if (use_atomic) {
                    atomicAdd(&C[(size_t)row*ldc + col],       v0);
                    atomicAdd(&C[(size_t)row*ldc + col + 1],   v1);
                    atomicAdd(&C[(size_t)(row+8)*ldc + col],   v2);
                    atomicAdd(&C[(size_t)(row+8)*ldc + col+1], v3);
                } else {
                    *(float2*)&C[(size_t)row*ldc + col]     = make_float2(v0, v1);
                    *(float2*)&C[(size_t)(row+8)*ldc + col] = make_float2(v2, v3);
                }
            }
        }
    }
}

// ---------------- rolling-window conv + SiLU, fine-grained t-chunks --------
// t-chunk = 16 steps -> grid (64, CB, 2) = 512 blocks; 19 loads/thread.
#define CONV_TCH 16
__global__ void __launch_bounds__(256)
conv_silu_kernel(const uint2* __restrict__ xzh4,
                 const float4* __restrict__ cw0, const float4* __restrict__ cb0,
                 const float4* __restrict__ cw1, const float4* __restrict__ cb1,
                 uint2* __restrict__ xch)
{
    const int e4  = (blockIdx.x & 1) * 256 + threadIdx.x;
    const int tc  = blockIdx.x >> 1;            // t-chunk 0..31
    const int b   = blockIdx.y;
    const int dir = blockIdx.z;
    const int t0  = tc * CONV_TCH;

    const float4* cw = dir ? cw1 : cw0;
    const float4 bi = (dir ? cb1 : cb0)[e4];
    const float4 w0 = cw[e4*4+0], w1 = cw[e4*4+1], w2 = cw[e4*4+2], w3 = cw[e4*4+3];

    auto ldx = [&](int ts) -> float4 {
        if (ts < 0) return make_float4(0.f, 0.f, 0.f, 0.f);
        int tg = dir ? (CL-1-ts) : ts;
        return h4f(xzh4[(size_t)((b << 9) + tg) * 1024 + e4]);
    };

    float4 p3 = ldx(t0-3), p2 = ldx(t0-2), p1 = ldx(t0-1);

#pragma unroll 4
    for (int tt = t0; tt < t0 + CONV_TCH; tt++) {
        float4 cur = ldx(tt);
        float a0 = bi.x, a1 = bi.y, a2 = bi.z, a3 = bi.w;
        a0 = fmaf(w0.x, p3.x, a0); a0 = fmaf(w0.y, p2.x, a0);
        a0 = fmaf(w0.z, p1.x, a0); a0 = fmaf(w0.w, cur.x, a0);
        a1 = fmaf(w1.x, p3.y, a1); a1 = fmaf(w1.y, p2.y, a1);
        a1 = fmaf(w1.z, p1.y, a1); a1 = fmaf(w1.w, cur.y, a1);
        a2 = fmaf(w2.x, p3.z, a2); a2 = fmaf(w2.y, p2.z, a2);
        a2 = fmaf(w2.z, p1.z, a2); a2 = fmaf(w2.w, cur.z, a2);
        a3 = fmaf(w3.x, p3.w, a3); a3 = fmaf(w3.y, p2.w, a3);
        a3 = fmaf(w3.z, p1.w, a3); a3 = fmaf(w3.w, cur.w, a3);
        p3 = p2; p2 = p1; p1 = cur;
        __half2 lo = __floats2half2_rn(siluf(a0), siluf(a1));
        __half2 hi = __floats2half2_rn(siluf(a2), siluf(a3));
        xch[(dir << 20) + (b << 18) + (tt << 9) + e4] =
            make_uint2(*(uint32_t*)&lo, *(uint32_t*)&hi);
    }
}

// ---------------- selective scan (half inputs, half output) ----------------
#define SCAN_TC 16
__global__ void __launch_bounds__(128)
scan_kernel(const __half* __restrict__ delta,
            const __half* __restrict__ xc,
            const float* __restrict__ dbc,
            const __half* __restrict__ xz,
            const float* __restrict__ A_log_f, const float* __restrict__ A_log_b,
            const float* __restrict__ Dp_f,    const float* __restrict__ Dp_b,
            __half* __restrict__ y)
{
    __shared__ float sD[SCAN_TC][128];
    __shared__ float sX[SCAN_TC][128];
    __shared__ float sZ[SCAN_TC][128];
    __shared__ float sB[SCAN_TC][CNS];
    __shared__ float sC[SCAN_TC][CNS];

    const int e   = blockIdx.x * 128 + threadIdx.x;
    const int b   = blockIdx.y;
    const int dir = blockIdx.z;
    const int tx  = threadIdx.x;

    const __half* dlt = delta + (size_t)dir * BLED;
    const __half* xcd = xc    + (size_t)dir * BLED;
    const float*  dbd = dbc   + (size_t)dir * CML * 96;
    __half*       yd  = y     + (size_t)dir * BLED;
    const float* A_log = dir ? A_log_b : A_log_f;
    const float* Dp    = dir ? Dp_b    : Dp_f;

    float Areg[CNS];
    bool fastok = true;
#pragma unroll
    for (int n = 0; n < CNS; n++) {
        float a = -__expf(A_log[e*CNS + n]);
        Areg[n] = a * 1.4426950408889634f;
        fastok = fastok && (fabsf(a + (float)(n+1)) < 1e-3f * (float)(n+1));
    }
    const bool fastA = __syncthreads_and(fastok);
    const float Dpe = Dp[e];

    float h[CNS];
#pragma unroll
    for (int n = 0; n < CNS; n++) h[n] = 0.f;

    auto run = [&](auto FC) {
        constexpr bool FAST = decltype(FC)::v;
        for (int t0 = 0; t0 < CL; t0 += SCAN_TC) {
            __syncthreads();
#pragma unroll
            for (int it = 0; it < SCAN_TC; it++) {
                int t = t0 + it;
                size_t r = (size_t)(b*CL + t) * CED + e;
                sD[it][tx] = __half2float(dlt[r]);
                sX[it][tx] = __half2float(xcd[r]);
                int tz = dir ? (CL-1-t) : t;
                sZ[it][tx] = __half2float(xz[((size_t)(b*CL + tz) << 12) + CED + e]);
            }
            for (int j = tx; j < SCAN_TC*CNS; j += 128) {
                int it = j >> 4, n = j & (CNS-1);
                size_t r = (size_t)(b*CL + t0 + it) * 96;
                sB[it][n] = dbd[r + CRK + n];
                sC[it][n] = dbd[r + CRK + CNS + n];
            }
            __syncthreads();

#pragma unroll
            for (int it = 0; it < SCAN_TC; it++) {
                float d  = sD[it][tx];
                float xv = sX[it][tx];
                float dx = d * xv;
                float dA[CNS];
                if (FAST) {
                    float r1 = ex2f(-1.4426950408889634f * d);   // exp(-d)
                    float r2 = r1*r1, r3 = r2*r1, r4 = r2*r2;
                    float r8 = r4*r4, r12 = r8*r4;
                    dA[0]=r1;      dA[1]=r2;      dA[2]=r3;      dA[3]=r4;
                    dA[4]=r4*r1;   dA[5]=r4*r2;   dA[6]=r4*r3;   dA[7]=r8;
                    dA[8]=r8*r1;   dA[9]=r8*r2;   dA[10]=r8*r3;  dA[11]=r8*r4;
                    dA[12]=r12*r1; dA[13]=r12*r2; dA[14]=r12*r3; dA[15]=r8*r8;
                } else {
#pragma unroll
                    for (int n = 0; n < CNS; n++) dA[n] = ex2f(d * Areg[n]);
                }
                float y0 = 0.f, y1 = 0.f, y2 = 0.f, y3 = 0.f;
#pragma unroll
                for (int n = 0; n < CNS; n += 4) {
                    h[n+0] = fmaf(dA[n+0], h[n+0], dx * sB[it][n+0]);
                    h[n+1] = fmaf(dA[n+1], h[n+1], dx * sB[it][n+1]);
                    h[n+2] = fmaf(dA[n+2], h[n+2], dx * sB[it][n+2]);
                    h[n+3] = fmaf(dA[n+3], h[n+3], dx * sB[it][n+3]);
                    y0 = fmaf(h[n+0], sC[it][n+0], y0);
                    y1 = fmaf(h[n+1], sC[it][n+1], y1);
                    y2 = fmaf(h[n+2], sC[it][n+2], y2);
                    y3 = fmaf(h[n+3], sC[it][n+3], y3);
                }
                float zv = sZ[it][tx];
                float yo = ((y0+y1) + (y2+y3)) + Dpe * xv;
                yd[(size_t)(b*CL + t0 + it)*CED + e] = __float2half_rn(yo * siluf(zv));
            }
        }
    };
    if (fastA) run(BC<true>{});
    else       run(BC<false>{});
}

// ---------------- combine (half2 in, half2 out) ------------------
__global__ void combine_kernel(const __half2* __restrict__ y0,
                               const __half2* __restrict__ y1,
                               __half2* __restrict__ yc)
{
    int idx = blockIdx.x * blockDim.x + threadIdx.x;
    int e2 = idx & (CED/2 - 1);
    int t  = (idx >> 10) & (CL-1);
    int b  = idx >> 19;
    float2 a  = __half22float2(y0[idx]);
    float2 bb = __half22float2(y1[(size_t)(b*CL + (CL-1-t))*(CED/2) + e2]);
    yc[idx] = __floats2half2_rn(0.5f*(a.x + bb.x), 0.5f*(a.y + bb.y));
}

// ---------------- launch ----------------
extern "C" void kernel_launch(void* const* d_in, const int* in_sizes, int n_in,
                              void* d_out, int out_size)
{
    const float* x      = (const float*)d_in[0];
    const float* W_in   = (const float*)d_in[1];
    const float* conv_w = (const float*)d_in[2];
    const float* conv_b = (const float*)d_in[3];
    const float* Wx     = (const float*)d_in[4];
    const float* Wdt    = (const float*)d_in[5];
    const float* b_dt   = (const float*)d_in[6];
    const float* A_log  = (const float*)d_in[7];
    const float* Dp     = (const float*)d_in[8];
    const float* conv_w_b = (const float*)d_in[9];
    const float* conv_b_b = (const float*)d_in[10];
    const float* Wx_b   = (const float*)d_in[11];
    const float* Wdt_b  = (const float*)d_in[12];
    const float* b_dt_b = (const float*)d_in[13];
    const float* A_log_b= (const float*)d_in[14];
    const float* Dp_b   = (const float*)d_in[15];
    const float* W_out  = (const float*)d_in[16];
    float* out = (float*)d_out;

    float *p_dbc;
    __half *p_xzh, *p_xch, *p_dbch, *p_deltah, *p_yh, *p_ych, *p_xh, *p_wh;
    cudaGetSymbolAddress((void**)&p_xzh,    g_xzh);
    cudaGetSymbolAddress((void**)&p_xch,    g_xch);
    cudaGetSymbolAddress((void**)&p_dbc,    g_dbc);
    cudaGetSymbolAddress((void**)&p_dbch,   g_dbch);
    cudaGetSymbolAddress((void**)&p_deltah, g_deltah);
    cudaGetSymbolAddress((void**)&p_yh,     g_yh);
    cudaGetSymbolAddress((void**)&p_ych,    g_ych);
    cudaGetSymbolAddress((void**)&p_xh,     g_xh);
    cudaGetSymbolAddress((void**)&p_wh,     g_wh);

    constexpr int SMEM128 = GNS*(128+128)*LDKH*2;   // 110592
    constexpr int SMEM96  = GNS*(128+96) *LDKH*2;   //  96768
    cudaFuncSetAttribute(gemm_f16w32<0,true>,    cudaFuncAttributeMaxDynamicSharedMemorySize, SMEM128);
    cudaFuncSetAttribute(gemm_f16w32<3,false>,   cudaFuncAttributeMaxDynamicSharedMemorySize, SMEM128);
    cudaFuncSetAttribute(gemm_f16<128,1,2,true>, cudaFuncAttributeMaxDynamicSharedMemorySize, SMEM128);
    cudaFuncSetAttribute(gemm_f16<96,0,1,false>, cudaFuncAttributeMaxDynamicSharedMemorySize, SMEM96);

    // 0) merged conversion / zero pass (also zeroes d_out for split-K atomics)
    cvt_all_k<<<(CVT_TOTAL + 255)/256, 256>>>(
        (const float4*)x, (const float4*)W_in, (const float4*)W_out,
        (const float4*)Wx, (const float4*)Wx_b, (const float4*)Wdt, (const float4*)Wdt_b,
        (uint2*)p_xh, (uint2*)p_wh, (float4*)p_dbc, (float4*)out);

    // 1) xz = x @ W_in^T  -> half output
    gemm_f16w32<0,true><<<dim3(32,16,1), 512, SMEM128>>>(
        p_xh, CD, p_wh+OW_IN, CD, p_xzh, 2*CED, CD);

    // 2) conv + silu (half in, half out, fine-grained rolling window)
    conv_silu_kernel<<<dim3(2*(CL/CONV_TCH), CB, 2), 256>>>(
        (const uint2*)p_xzh, (const float4*)conv_w, (const float4*)conv_b,
        (const float4*)conv_w_b, (const float4*)conv_b_b, (uint2*)p_xch);

    // 3) dbc = xc @ Wx^T (both dirs, split-K=8, fp32 atomics)
    gemm_f16<96,0,1,false><<<dim3(2,16,8), 192, SMEM96>>>(
        p_xch, CED, (size_t)BLED, p_wh+OWX_F, p_wh+OWX_B, CED,
        p_dbc, 96, (size_t)CML*96, CED, nullptr, nullptr);

    // 3b) dbc -> half (delta GEMM A operand)
    f2h_k<<<(2*CML*96/2 + 255)/256, 256>>>((const float2*)p_dbc, (__half2*)p_dbch, 2*CML*96/2);

    // 4) delta = softplus(dbc[:, :64] @ Wdt^T + b_dt) -> half
    gemm_f16<128,1,2,true><<<dim3(16,16,2), 256, SMEM128>>>(
        p_dbch, 96, (size_t)CML*96, p_wh+OWDT_F, p_wh+OWDT_B, CRK,
        p_deltah, CED, (size_t)BLED, CRK, b_dt, b_dt_b);

    // 5) selective scan + gating, both dirs (fast-exp) -> half
    scan_kernel<<<dim3(CED/128, CB, 2), 128>>>(
        p_deltah, p_xch, p_dbc, p_xzh, A_log, A_log_b, Dp, Dp_b, p_yh);

    // 6) combine -> half
    combine_kernel<<<(BLED/2)/256, 256>>>(
        (const __half2*)p_yh, (const __half2*)(p_yh + BLED), (__half2*)p_ych);

    // 7) out = yc @ W_out^T (split-K=2, fp32 atomics into d_out)
    gemm_f16w32<3,false><<<dim3(8,16,2), 512, SMEM128>>>(
        p_ych, CED, p_wh+OW_OUT, CED, out, CD, CED);
}

// round 16
// speedup vs baseline: 1.4459x; 1.2085x over previous
#include <cuda_runtime.h>
#include <cuda_fp16.h>
#include <cstdint>

// ---------------- Problem constants ----------------
#define CB   4
#define CL   512
#define CD   1024
#define CED  2048
#define CNS  16
#define CRK  64
#define CKC  4
#define CML  (CB*CL)        // 2048
#define BLED (CB*CL*CED)    // 4194304
#define NCH  8              // scan time-chunks
#define TCH  (CL/NCH)       // 64 steps per chunk

// ---------------- Scratch ----------------
__device__ __half g_xzh[CB*CL*2*CED];
__device__ __half g_xch[2*BLED];
__device__ float  g_dbc[2*CML*96];
__device__ __half g_dbch[2*CML*96];
__device__ __half g_deltah[2*BLED];
__device__ __half g_yh[2*BLED];
__device__ __half g_ych[BLED];
__device__ __half g_xh[CML*CD];
__device__ __half g_wh[7077888];
__device__ float  g_hmid[2*CB*NCH*CNS*CED];   // chunk-local h
__device__ float  g_sd[2*CB*NCH*CED];         // chunk sum of delta
#define OW_IN   0
#define OW_OUT  4194304
#define OWX_F   6291456
#define OWX_B   6488064
#define OWDT_F  6684672
#define OWDT_B  6815744

// ---------------- helpers ----------------
__device__ __forceinline__ float softplusf(float x) {
    return fmaxf(x, 0.f) + log1pf(__expf(-fabsf(x)));
}
__device__ __forceinline__ float siluf(float x) {
    return x / (1.f + __expf(-x));
}
__device__ __forceinline__ float ex2f(float x) {
    float y; asm("ex2.approx.ftz.f32 %0, %1;" : "=f"(y) : "f"(x));
    return y;
}
__device__ __forceinline__ void cp16(uint32_t dst, const void* src) {
    asm volatile("cp.async.cg.shared.global [%0], [%1], 16;" :: "r"(dst), "l"(src));
}
__device__ __forceinline__ void ldsm4(uint32_t& r0, uint32_t& r1, uint32_t& r2, uint32_t& r3, uint32_t addr) {
    asm volatile("ldmatrix.sync.aligned.m8n8.x4.shared.b16 {%0,%1,%2,%3}, [%4];"
                 : "=r"(r0), "=r"(r1), "=r"(r2), "=r"(r3) : "r"(addr));
}
__device__ __forceinline__ uint2 f4h(float4 v) {
    __half2 lo = __floats2half2_rn(v.x, v.y);
    __half2 hi = __floats2half2_rn(v.z, v.w);
    return make_uint2(*(uint32_t*)&lo, *(uint32_t*)&hi);
}
__device__ __forceinline__ float4 h4f(uint2 u) {
    float2 lo = __half22float2(*(__half2*)&u.x);
    float2 hi = __half22float2(*(__half2*)&u.y);
    return make_float4(lo.x, lo.y, hi.x, hi.y);
}
template<bool B> struct BC { static constexpr bool v = B; };

// dA powers: given r = exp(-d) form values for A_n = -(n+1) (fast path)
__device__ __forceinline__ void dA_fast(float dA[CNS], float r1) {
    float r2 = r1*r1, r3 = r2*r1, r4 = r2*r2;
    float r8 = r4*r4, r12 = r8*r4;
    dA[0]=r1;      dA[1]=r2;      dA[2]=r3;      dA[3]=r4;
    dA[4]=r4*r1;   dA[5]=r4*r2;   dA[6]=r4*r3;   dA[7]=r8;
    dA[8]=r8*r1;   dA[9]=r8*r2;   dA[10]=r8*r3;  dA[11]=r8*r4;
    dA[12]=r12*r1; dA[13]=r12*r2; dA[14]=r12*r3; dA[15]=r8*r8;
}

// ---------------- conversion kernels (split for stream overlap) ------------
#define CVT_MAIN_TOTAL (524288+1048576)
__global__ void cvt_main_k(const float4* __restrict__ x, const float4* __restrict__ win,
                           uint2* __restrict__ xh, uint2* __restrict__ wh)
{
    int i = blockIdx.x * blockDim.x + threadIdx.x;
    if (i < 524288)  { xh[i] = f4h(x[i]); return; }                 i -= 524288;
    if (i < 1048576) wh[OW_IN/4 + i] = f4h(win[i]);
}
#define CVT_REST_TOTAL (524288+49152+49152+32768+32768+98304+524288)
__global__ void cvt_rest_k(const float4* __restrict__ wout,
                           const float4* __restrict__ wx,  const float4* __restrict__ wxb,
                           const float4* __restrict__ wdt, const float4* __restrict__ wdtb,
                           uint2* __restrict__ wh, float4* __restrict__ dbcz,
                           float4* __restrict__ outz)
{
    int i = blockIdx.x * blockDim.x + threadIdx.x;
    if (i < 524288)  { wh[OW_OUT/4 + i] = f4h(wout[i]); return; }   i -= 524288;
    if (i < 49152)   { wh[OWX_F/4  + i] = f4h(wx[i]);   return; }   i -= 49152;
    if (i < 49152)   { wh[OWX_B/4  + i] = f4h(wxb[i]);  return; }   i -= 49152;
    if (i < 32768)   { wh[OWDT_F/4 + i] = f4h(wdt[i]);  return; }   i -= 32768;
    if (i < 32768)   { wh[OWDT_B/4 + i] = f4h(wdtb[i]); return; }   i -= 32768;
    if (i < 98304)   { dbcz[i] = make_float4(0.f,0.f,0.f,0.f); return; } i -= 98304;
    if (i < 524288)  outz[i] = make_float4(0.f, 0.f, 0.f, 0.f);
}

__global__ void f2h_k(const float2* __restrict__ in, __half2* __restrict__ out, int n2) {
    int i = blockIdx.x * blockDim.x + threadIdx.x;
    if (i < n2) {
        float2 v = in[i];
        out[i] = __floats2half2_rn(v.x, v.y);
    }
}

#define LDKH 72
#define GNS  3

// ================= 8-warp FP16 GEMM (dbc / delta) =================
template<int BN, int EPI, int DIRAX, bool OUTH>
__global__ void __launch_bounds__(2*(BN/32)*32)
gemm_f16(const __half* __restrict__ A, int lda, size_t aStride,
         const __half* __restrict__ B0, const __half* __restrict__ B1, int ldb,
         void* __restrict__ Craw, int ldc, size_t cStride,
         int K, const float* __restrict__ bias0, const float* __restrict__ bias1)
{
    constexpr int BM = 128;
    constexpr int WARPS_N = BN/32;
    constexpr int THREADS = 2*WARPS_N*32;
    constexpr int STAGE_H = (BM+BN)*LDKH;
    extern __shared__ __half smh[];

    const int tid  = threadIdx.x;
    const int warp = tid >> 5, lane = tid & 31;
    const int wm = warp / WARPS_N, wn = warp % WARPS_N;
    const int g = lane >> 2, t = lane & 3;

    const int dir = (DIRAX==1) ? blockIdx.x : (DIRAX==2 ? blockIdx.z : 0);
    const int row0 = blockIdx.y * BM;
    const int col0 = (DIRAX==1) ? 0 : blockIdx.x * BN;
    const int nsplit = (DIRAX==1) ? gridDim.z : 1;
    const int Kc = K / nsplit;
    const int kbase = (DIRAX==1) ? blockIdx.z * Kc : 0;
    const int KT = Kc / 64;

    const __half* Aeff = A + (size_t)dir * aStride;
    const __half* Beff = dir ? B1 : B0;
    const float*  bias = dir ? bias1 : bias0;

    float acc[4][4][4];
#pragma unroll
    for (int i = 0; i < 4; i++)
#pragma unroll
        for (int j = 0; j < 4; j++)
#pragma unroll
            for (int q = 0; q < 4; q++) acc[i][j][q] = 0.f;

    const uint32_t smem0 = (uint32_t)__cvta_generic_to_shared(smh);
    const uint32_t aLane = (uint32_t)(((wm*64 + (lane & 7) + ((lane >> 3) & 1) * 8) * LDKH
                                     + (lane >> 4) * 8) * 2);
    const uint32_t bLane = (uint32_t)((BM*LDKH
                                     + (wn*32 + (lane & 7) + ((lane >> 4) & 1) * 8) * LDKH
                                     + ((lane >> 3) & 1) * 8) * 2);

    auto load_tile = [&](int kt, int s) {
        __half* As = smh + s*STAGE_H;
        __half* Bs = As + BM*LDKH;
        const int k0 = kbase + kt*64;
#pragma unroll 2
        for (int i = tid; i < BM*8; i += THREADS) {
            int m = i >> 3, kq = (i & 7) << 3;
            cp16((uint32_t)__cvta_generic_to_shared(As + m*LDKH + kq),
                 Aeff + (size_t)(row0+m)*lda + k0 + kq);
        }
#pragma unroll 2
        for (int i = tid; i < BN*8; i += THREADS) {
            int n = i >> 3, kq = (i & 7) << 3;
            cp16((uint32_t)__cvta_generic_to_shared(Bs + n*LDKH + kq),
                 Beff + (size_t)(col0+n)*ldb + k0 + kq);
        }
    };

    auto comp = [&](int s) {
        const uint32_t base = smem0 + (uint32_t)(s*STAGE_H)*2u;
#pragma unroll
        for (int ks = 0; ks < 4; ks++) {
            const uint32_t kb = (uint32_t)(ks*16)*2u;
            uint32_t a[4][4], b[2][4];
#pragma unroll
            for (int mt = 0; mt < 4; mt++)
                ldsm4(a[mt][0], a[mt][1], a[mt][2], a[mt][3],
                      base + aLane + (uint32_t)(mt*16*LDKH)*2u + kb);
#pragma unroll
            for (int np = 0; np < 2; np++)
                ldsm4(b[np][0], b[np][1], b[np][2], b[np][3],
                      base + bLane + (uint32_t)(np*16*LDKH)*2u + kb);
#pragma unroll
            for (int mt = 0; mt < 4; mt++)
#pragma unroll
                for (int nt = 0; nt < 4; nt++) {
                    const uint32_t bb0 = b[nt>>1][(nt&1)*2 + 0];
                    const uint32_t bb1 = b[nt>>1][(nt&1)*2 + 1];
                    asm volatile(
                        "mma.sync.aligned.m16n8k16.row.col.f32.f16.f16.f32 "
                        "{%0,%1,%2,%3}, {%4,%5,%6,%7}, {%8,%9}, {%0,%1,%2,%3};"
                        : "+f"(acc[mt][nt][0]), "+f"(acc[mt][nt][1]),
                          "+f"(acc[mt][nt][2]), "+f"(acc[mt][nt][3])
                        : "r"(a[mt][0]), "r"(a[mt][1]), "r"(a[mt][2]), "r"(a[mt][3]),
                          "r"(bb0), "r"(bb1));
                }
        }
    };

    load_tile(0, 0);
    asm volatile("cp.async.commit_group;");
    if (KT > 1) load_tile(1, 1);
    asm volatile("cp.async.commit_group;");

    for (int kt = 0; kt < KT; kt++) {
        asm volatile("cp.async.wait_group 1;");
        __syncthreads();
        if (kt + 2 < KT) load_tile(kt + 2, (kt + 2) % GNS);
        asm volatile("cp.async.commit_group;");
        comp(kt % GNS);
    }

    const bool use_atomic = (DIRAX == 1 && nsplit > 1);
#pragma unroll
    for (int mt = 0; mt < 4; mt++) {
        int row = row0 + wm*64 + mt*16 + g;
#pragma unroll
        for (int nt = 0; nt < 4; nt++) {
            int col = col0 + wn*32 + nt*8 + 2*t;
            float v0 = acc[mt][nt][0], v1 = acc[mt][nt][1];
            float v2 = acc[mt][nt][2], v3 = acc[mt][nt][3];
            if (EPI == 1) {
                v0 = softplusf(v0 + bias[col]);
                v1 = softplusf(v1 + bias[col+1]);
                v2 = softplusf(v2 + bias[col]);
                v3 = softplusf(v3 + bias[col+1]);
            }
            if (OUTH) {
                __half* Ceff = (__half*)Craw + (size_t)dir * cStride;
                *(__half2*)&Ceff[(size_t)row*ldc + col]     = __floats2half2_rn(v0, v1);
                *(__half2*)&Ceff[(size_t)(row+8)*ldc + col] = __floats2half2_rn(v2, v3);
            } else {
                float* Ceff = (float*)Craw + (size_t)dir * cStride;
                if (use_atomic) {
                    atomicAdd(&Ceff[(size_t)row*ldc + col],       v0);
                    atomicAdd(&Ceff[(size_t)row*ldc + col + 1],   v1);
                    atomicAdd(&Ceff[(size_t)(row+8)*ldc + col],   v2);
                    atomicAdd(&Ceff[(size_t)(row+8)*ldc + col+1], v3);
                } else {
                    *(float2*)&Ceff[(size_t)row*ldc + col]     = make_float2(v0, v1);
                    *(float2*)&Ceff[(size_t)(row+8)*ldc + col] = make_float2(v2, v3);
                }
            }
        }
    }
}

// ================= 16-warp FP16 GEMM (xz / out) ===========
template<int DIRAX, bool OUTH>
__global__ void __launch_bounds__(512, 2)
gemm_f16w32(const __half* __restrict__ A, int lda,
            const __half* __restrict__ B, int ldb,
            void* __restrict__ Craw, int ldc, int K)
{
    constexpr int BM = 128, BN = 128, THREADS = 512;
    constexpr int STAGE_H = (BM+BN)*LDKH;
    extern __shared__ __half smh[];

    const int tid  = threadIdx.x;
    const int warp = tid >> 5, lane = tid & 31;
    const int wm = warp >> 2, wn = warp & 3;
    const int g = lane >> 2, t = lane & 3;

    const int row0 = blockIdx.y * BM;
    const int col0 = blockIdx.x * BN;
    const int nsplit = (DIRAX==3) ? gridDim.z : 1;
    const int Kc = K / nsplit;
    const int kbase = (DIRAX==3) ? blockIdx.z * Kc : 0;
    const int KT = Kc / 64;

    float acc[2][4][4];
#pragma unroll
    for (int i = 0; i < 2; i++)
#pragma unroll
        for (int j = 0; j < 4; j++)
#pragma unroll
            for (int q = 0; q < 4; q++) acc[i][j][q] = 0.f;

    const uint32_t smem0 = (uint32_t)__cvta_generic_to_shared(smh);
    const uint32_t aLane = (uint32_t)(((wm*32 + (lane & 7) + ((lane >> 3) & 1) * 8) * LDKH
                                     + (lane >> 4) * 8) * 2);
    const uint32_t bLane = (uint32_t)((BM*LDKH
                                     + (wn*32 + (lane & 7) + ((lane >> 4) & 1) * 8) * LDKH
                                     + ((lane >> 3) & 1) * 8) * 2);

    auto load_tile = [&](int kt, int s) {
        __half* As = smh + s*STAGE_H;
        __half* Bs = As + BM*LDKH;
        const int k0 = kbase + kt*64;
#pragma unroll 2
        for (int i = tid; i < BM*8; i += THREADS) {
            int m = i >> 3, kq = (i & 7) << 3;
            cp16((uint32_t)__cvta_generic_to_shared(As + m*LDKH + kq),
                 A + (size_t)(row0+m)*lda + k0 + kq);
        }
#pragma unroll 2
        for (int i = tid; i < BN*8; i += THREADS) {
            int n = i >> 3, kq = (i & 7) << 3;
            cp16((uint32_t)__cvta_generic_to_shared(Bs + n*LDKH + kq),
                 B + (size_t)(col0+n)*ldb + k0 + kq);
        }
    };

    auto comp = [&](int s) {
        const uint32_t base = smem0 + (uint32_t)(s*STAGE_H)*2u;
#pragma unroll
        for (int ks = 0; ks < 4; ks++) {
            const uint32_t kb = (uint32_t)(ks*16)*2u;
            uint32_t a[2][4], b[2][4];
#pragma unroll
            for (int mt = 0; mt < 2; mt++)
                ldsm4(a[mt][0], a[mt][1], a[mt][2], a[mt][3],
                      base + aLane + (uint32_t)(mt*16*LDKH)*2u + kb);
#pragma unroll
            for (int np = 0; np < 2; np++)
                ldsm4(b[np][0], b[np][1], b[np][2], b[np][3],
                      base + bLane + (uint32_t)(np*16*LDKH)*2u + kb);
#pragma unroll
            for (int mt = 0; mt < 2; mt++)
#pragma unroll
                for (int nt = 0; nt < 4; nt++) {
                    const uint32_t bb0 = b[nt>>1][(nt&1)*2 + 0];
                    const uint32_t bb1 = b[nt>>1][(nt&1)*2 + 1];
                    asm volatile(
                        "mma.sync.aligned.m16n8k16.row.col.f32.f16.f16.f32 "
                        "{%0,%1,%2,%3}, {%4,%5,%6,%7}, {%8,%9}, {%0,%1,%2,%3};"
                        : "+f"(acc[mt][nt][0]), "+f"(acc[mt][nt][1]),
                          "+f"(acc[mt][nt][2]), "+f"(acc[mt][nt][3])
                        : "r"(a[mt][0]), "r"(a[mt][1]), "r"(a[mt][2]), "r"(a[mt][3]),
                          "r"(bb0), "r"(bb1));
                }
        }
    };

    load_tile(0, 0);
    asm volatile("cp.async.commit_group;");
    if (KT > 1) load_tile(1, 1);
    asm volatile("cp.async.commit_group;");

    for (int kt = 0; kt < KT; kt++) {
        asm volatile("cp.async.wait_group 1;");
        __syncthreads();
        if (kt + 2 < KT) load_tile(kt + 2, (kt + 2) % GNS);
        asm volatile("cp.async.commit_group;");
        comp(kt % GNS);
    }

    const bool use_atomic = (DIRAX == 3 && nsplit > 1);
#pragma unroll
    for (int mt = 0; mt < 2; mt++) {
        int row = row0 + wm*32 + mt*16 + g;
#pragma unroll
        for (int nt = 0; nt < 4; nt++) {
            int col = col0 + wn*32 + nt*8 + 2*t;
            float v0 = acc[mt][nt][0], v1 = acc[mt][nt][1];
            float v2 = acc[mt][nt][2], v3 = acc[mt][nt][3];
            if (OUTH) {
                __half* C = (__half*)Craw;
                *(__half2*)&C[(size_t)row*ldc + col]     = __floats2half2_rn(v0, v1);
                *(__half2*)&C[(size_t)(row+8)*ldc + col] = __floats2half2_rn(v2, v3);
            } else {
                float* C = (float*)Craw;
                if (use_atomic) {
                    atomicAdd(&C[(size_t)row*ldc + col],       v0);
                    atomicAdd(&C[(size_t)row*ldc + col + 1],   v1);
                    atomicAdd(&C[(size_t)(row+8)*ldc + col],   v2);
                    atomicAdd(&C[(size_t)(row+8)*ldc + col+1], v3);
                } else {
                    *(float2*)&C[(size_t)row*ldc + col]     = make_float2(v0, v1);
                    *(float2*)&C[(size_t)(row+8)*ldc + col] = make_float2(v2, v3);
                }
            }
        }
    }
}

// ---------------- rolling-window conv + SiLU (fine-grained) ---------------
#define CONV_TCH 16
__global__ void __launch_bounds__(256)
conv_silu_kernel(const uint2* __restrict__ xzh4,
                 const float4* __restrict__ cw0, const float4* __restrict__ cb0,
                 const float4* __restrict__ cw1, const float4* __restrict__ cb1,
                 uint2* __restrict__ xch)
{
    const int e4  = (blockIdx.x & 1) * 256 + threadIdx.x;
    const int tc  = blockIdx.x >> 1;
    const int b   = blockIdx.y;
    const int dir = blockIdx.z;
    const int t0  = tc * CONV_TCH;

    const float4* cw = dir ? cw1 : cw0;
    const float4 bi = (dir ? cb1 : cb0)[e4];
    const float4 w0 = cw[e4*4+0], w1 = cw[e4*4+1], w2 = cw[e4*4+2], w3 = cw[e4*4+3];

    auto ldx = [&](int ts) -> float4 {
        if (ts < 0) return make_float4(0.f, 0.f, 0.f, 0.f);
        int tg = dir ? (CL-1-ts) : ts;
        return h4f(xzh4[(size_t)((b << 9) + tg) * 1024 + e4]);
    };

    float4 p3 = ldx(t0-3), p2 = ldx(t0-2), p1 = ldx(t0-1);

#pragma unroll 4
    for (int tt = t0; tt < t0 + CONV_TCH; tt++) {
        float4 cur = ldx(tt);
        float a0 = bi.x, a1 = bi.y, a2 = bi.z, a3 = bi.w;
        a0 = fmaf(w0.x, p3.x, a0); a0 = fmaf(w0.y, p2.x, a0);
        a0 = fmaf(w0.z, p1.x, a0); a0 = fmaf(w0.w, cur.x, a0);
        a1 = fmaf(w1.x, p3.y, a1); a1 = fmaf(w1.y, p2.y, a1);
        a1 = fmaf(w1.z, p1.y, a1); a1 = fmaf(w1.w, cur.y, a1);
        a2 = fmaf(w2.x, p3.z, a2); a2 = fmaf(w2.y, p2.z, a2);
        a2 = fmaf(w2.z, p1.z, a2); a2 = fmaf(w2.w, cur.z, a2);
        a3 = fmaf(w3.x, p3.w, a3); a3 = fmaf(w3.y, p2.w, a3);
        a3 = fmaf(w3.z, p1.w, a3); a3 = fmaf(w3.w, cur.w, a3);
        p3 = p2; p2 = p1; p1 = cur;
        __half2 lo = __floats2half2_rn(siluf(a0), siluf(a1));
        __half2 hi = __floats2half2_rn(siluf(a2), siluf(a3));
        xch[(dir << 20) + (b << 18) + (tt << 9) + e4] =
            make_uint2(*(uint32_t*)&lo, *(uint32_t*)&hi);
    }
}

// ---------------- scan phase 1: chunk-local partial scans ------------------
#define SCAN_TC 16
__global__ void __launch_bounds__(128)
scan_p1(const __half* __restrict__ delta,
        const __half* __restrict__ xc,
        const float* __restrict__ dbc,
        const float* __restrict__ A_log_f, const float* __restrict__ A_log_b,
        float* __restrict__ hmid, float* __restrict__ sdbuf)
{
    __shared__ float sD[SCAN_TC][128];
    __shared__ float sX[SCAN_TC][128];
    __shared__ float sB[SCAN_TC][CNS];

    const int e   = blockIdx.x * 128 + threadIdx.x;
    const int b   = blockIdx.y;
    const int dir = blockIdx.z >> 3;
    const int c   = blockIdx.z & 7;
    const int tx  = threadIdx.x;

    const __half* dlt = delta + (size_t)dir * BLED;
    const __half* xcd = xc    + (size_t)dir * BLED;
    const float*  dbd = dbc   + (size_t)dir * CML * 96;
    const float* A_log = dir ? A_log_b : A_log_f;

    float Areg[CNS];
    bool fastok = true;
#pragma unroll
    for (int n = 0; n < CNS; n++) {
        float a = -__expf(A_log[e*CNS + n]);
        Areg[n] = a * 1.4426950408889634f;
        fastok = fastok && (fabsf(a + (float)(n+1)) < 1e-3f * (float)(n+1));
    }
    const bool fastA = __syncthreads_and(fastok);

    float h[CNS];
#pragma unroll
    for (int n = 0; n < CNS; n++) h[n] = 0.f;
    float sd = 0.f;

    auto run = [&](auto FC) {
        constexpr bool FAST = decltype(FC)::v;
        for (int t0 = c*TCH; t0 < (c+1)*TCH; t0 += SCAN_TC) {
            __syncthreads();
#pragma unroll
            for (int it = 0; it < SCAN_TC; it++) {
                size_t r = (size_t)(b*CL + t0 + it) * CED + e;
                sD[it][tx] = __half2float(dlt[r]);
                sX[it][tx] = __half2float(xcd[r]);
            }
            for (int j = tx; j < SCAN_TC*CNS; j += 128) {
                int it = j >> 4, n = j & (CNS-1);
                sB[it][n] = dbd[(size_t)(b*CL + t0 + it) * 96 + CRK + n];
            }
            __syncthreads();
#pragma unroll
            for (int it = 0; it < SCAN_TC; it++) {
                float d  = sD[it][tx];
                float dx = d * sX[it][tx];
                sd += d;
                float dA[CNS];
                if (FAST) dA_fast(dA, ex2f(-1.4426950408889634f * d));
                else {
#pragma unroll
                    for (int n = 0; n < CNS; n++) dA[n] = ex2f(d * Areg[n]);
                }
#pragma unroll
                for (int n = 0; n < CNS; n++)
                    h[n] = fmaf(dA[n], h[n], dx * sB[it][n]);
            }
        }
    };
    if (fastA) run(BC<true>{});
    else       run(BC<false>{});

    const int base = ((dir*CB + b)*NCH + c);
#pragma unroll
    for (int n = 0; n < CNS; n++)
        hmid[((size_t)base*CNS + n)*CED + e] = h[n];
    sdbuf[(size_t)base*CED + e] = sd;
}

// ---------------- scan phase 2: fold h_in, scan chunk, emit y --------------
__global__ void __launch_bounds__(128)
scan_p2(const __half* __restrict__ delta,
        const __half* __restrict__ xc,
        const float* __restrict__ dbc,
        const __half* __restrict__ xz,
        const float* __restrict__ A_log_f, const float* __restrict__ A_log_b,
        const float* __restrict__ Dp_f,    const float* __restrict__ Dp_b,
        const float* __restrict__ hmid, const float* __restrict__ sdbuf,
        __half* __restrict__ y)
{
    __shared__ float sD[SCAN_TC][128];
    __shared__ float sX[SCAN_TC][128];
    __shared__ float sZ[SCAN_TC][128];
    __shared__ float sB[SCAN_TC][CNS];
    __shared__ float sC[SCAN_TC][CNS];

    const int e   = blockIdx.x * 128 + threadIdx.x;
    const int b   = blockIdx.y;
    const int dir = blockIdx.z >> 3;
    const int c   = blockIdx.z & 7;
    const int tx  = threadIdx.x;

    const __half* dlt = delta + (size_t)dir * BLED;
    const __half* xcd = xc    + (size_t)dir * BLED;
    const float*  dbd = dbc   + (size_t)dir * CML * 96;
    __half*       yd  = y     + (size_t)dir * BLED;
    const float* A_log = dir ? A_log_b : A_log_f;
    const float* Dp    = dir ? Dp_b    : Dp_f;

    float Areg[CNS];
    bool fastok = true;
#pragma unroll
    for (int n = 0; n < CNS; n++) {
        float a = -__expf(A_log[e*CNS + n]);
        Areg[n] = a * 1.4426950408889634f;
        fastok = fastok && (fabsf(a + (float)(n+1)) < 1e-3f * (float)(n+1));
    }
    const bool fastA = __syncthreads_and(fastok);
    const float Dpe = Dp[e];

    // fold h_in across previous chunks
    float h[CNS];
#pragma unroll
    for (int n = 0; n < CNS; n++) h[n] = 0.f;
    for (int cp = 0; cp < c; cp++) {
        const int base = ((dir*CB + b)*NCH + cp);
        float S = sdbuf[(size_t)base*CED + e];
        float T[CNS];
        if (fastA) dA_fast(T, ex2f(-1.4426950408889634f * S));
        else {
#pragma unroll
            for (int n = 0; n < CNS; n++) T[n] = ex2f(S * Areg[n]);
        }
#pragma unroll
        for (int n = 0; n < CNS; n++)
            h[n] = fmaf(T[n], h[n], hmid[((size_t)base*CNS + n)*CED + e]);
    }

    auto run = [&](auto FC) {
        constexpr bool FAST = decltype(FC)::v;
        for (int t0 = c*TCH; t0 < (c+1)*TCH; t0 += SCAN_TC) {
            __syncthreads();
#pragma unroll
            for (int it = 0; it < SCAN_TC; it++) {
                int t = t0 + it;
                size_t r = (size_t)(b*CL + t) * CED + e;
                sD[it][tx] = __half2float(dlt[r]);
                sX[it][tx] = __half2float(xcd[r]);
                int tz = dir ? (CL-1-t) : t;
                sZ[it][tx] = __half2float(xz[((size_t)(b*CL + tz) << 12) + CED + e]);
            }
            for (int j = tx; j < SCAN_TC*CNS; j += 128) {
                int it = j >> 4, n = j & (CNS-1);
                size_t r = (size_t)(b*CL + t0 + it) * 96;
                sB[it][n] = dbd[r + CRK + n];
                sC[it][n] = dbd[r + CRK + CNS + n];
            }
            __syncthreads();
#pragma unroll
            for (int it = 0; it < SCAN_TC; it++) {
                float d  = sD[it][tx];
                float xv = sX[it][tx];
                float dx = d * xv;
                float dA[CNS];
                if (FAST) dA_fast(dA, ex2f(-1.4426950408889634f * d));
                else {
#pragma unroll
                    for (int n = 0; n < CNS; n++) dA[n] = ex2f(d * Areg[n]);
                }
                float y0 = 0.f, y1 = 0.f, y2 = 0.f, y3 = 0.f;
#pragma unroll
                for (int n = 0; n < CNS; n += 4) {
                    h[n+0] = fmaf(dA[n+0], h[n+0], dx * sB[it][n+0]);
                    h[n+1] = fmaf(dA[n+1], h[n+1], dx * sB[it][n+1]);
                    h[n+2] = fmaf(dA[n+2], h[n+2], dx * sB[it][n+2]);
                    h[n+3] = fmaf(dA[n+3], h[n+3], dx * sB[it][n+3]);
                    y0 = fmaf(h[n+0], sC[it][n+0], y0);
                    y1 = fmaf(h[n+1], sC[it][n+1], y1);
                    y2 = fmaf(h[n+2], sC[it][n+2], y2);
                    y3 = fmaf(h[n+3], sC[it][n+3], y3);
                }
                float zv = sZ[it][tx];
                float yo = ((y0+y1) + (y2+y3)) + Dpe * xv;
                yd[(size_t)(b*CL + t0 + it)*CED + e] = __float2half_rn(yo * siluf(zv));
            }
        }
    };
    if (fastA) run(BC<true>{});
    else       run(BC<false>{});
}

// ---------------- combine (half2 in, half2 out) ------------------
__global__ void combine_kernel(const __half2* __restrict__ y0,
                               const __half2* __restrict__ y1,
                               __half2* __restrict__ yc)
{
    int idx = blockIdx.x * blockDim.x + threadIdx.x;
    int e2 = idx & (CED/2 - 1);
    int t  = (idx >> 10) & (CL-1);
    int b  = idx >> 19;
    float2 a  = __half22float2(y0[idx]);
    float2 bb = __half22float2(y1[(size_t)(b*CL + (CL-1-t))*(CED/2) + e2]);
    yc[idx] = __floats2half2_rn(0.5f*(a.x + bb.x), 0.5f*(a.y + bb.y));
}

// ---------------- launch ----------------
extern "C" void kernel_launch(void* const* d_in, const int* in_sizes, int n_in,
                              void* d_out, int out_size)
{
    const float* x      = (const float*)d_in[0];
    const float* W_in   = (const float*)d_in[1];
    const float* conv_w = (const float*)d_in[2];
    const float* conv_b = (const float*)d_in[3];
    const float* Wx     = (const float*)d_in[4];
    const float* Wdt    = (const float*)d_in[5];
    const float* b_dt   = (const float*)d_in[6];
    const float* A_log  = (const float*)d_in[7];
    const float* Dp     = (const float*)d_in[8];
    const float* conv_w_b = (const float*)d_in[9];
    const float* conv_b_b = (const float*)d_in[10];
    const float* Wx_b   = (const float*)d_in[11];
    const float* Wdt_b  = (const float*)d_in[12];
    const float* b_dt_b = (const float*)d_in[13];
    const float* A_log_b= (const float*)d_in[14];
    const float* Dp_b   = (const float*)d_in[15];
    const float* W_out  = (const float*)d_in[16];
    float* out = (float*)d_out;

    float *p_dbc, *p_hmid, *p_sd;
    __half *p_xzh, *p_xch, *p_dbch, *p_deltah, *p_yh, *p_ych, *p_xh, *p_wh;
    cudaGetSymbolAddress((void**)&p_xzh,    g_xzh);
    cudaGetSymbolAddress((void**)&p_xch,    g_xch);
    cudaGetSymbolAddress((void**)&p_dbc,    g_dbc);
    cudaGetSymbolAddress((void**)&p_dbch,   g_dbch);
    cudaGetSymbolAddress((void**)&p_deltah, g_deltah);
    cudaGetSymbolAddress((void**)&p_yh,     g_yh);
    cudaGetSymbolAddress((void**)&p_ych,    g_ych);
    cudaGetSymbolAddress((void**)&p_xh,     g_xh);
    cudaGetSymbolAddress((void**)&p_wh,     g_wh);
    cudaGetSymbolAddress((void**)&p_hmid,   g_hmid);
    cudaGetSymbolAddress((void**)&p_sd,     g_sd);

    constexpr int SMEM128 = GNS*(128+128)*LDKH*2;
    constexpr int SMEM96  = GNS*(128+96) *LDKH*2;
    cudaFuncSetAttribute(gemm_f16w32<0,true>,    cudaFuncAttributeMaxDynamicSharedMemorySize, SMEM128);
    cudaFuncSetAttribute(gemm_f16w32<3,false>,   cudaFuncAttributeMaxDynamicSharedMemorySize, SMEM128);
    cudaFuncSetAttribute(gemm_f16<128,1,2,true>, cudaFuncAttributeMaxDynamicSharedMemorySize, SMEM128);
    cudaFuncSetAttribute(gemm_f16<96,0,1,false>, cudaFuncAttributeMaxDynamicSharedMemorySize, SMEM96);

    static cudaStream_t s1 = nullptr;
    static cudaEvent_t  e0 = nullptr, e1 = nullptr;
    if (!s1) {
        cudaStreamCreateWithFlags(&s1, cudaStreamNonBlocking);
        cudaEventCreateWithFlags(&e0, cudaEventDisableTiming);
        cudaEventCreateWithFlags(&e1, cudaEventDisableTiming);
    }

    // 0a) convert xz-GEMM prerequisites
    cvt_main_k<<<(CVT_MAIN_TOTAL + 255)/256, 256>>>(
        (const float4*)x, (const float4*)W_in, (uint2*)p_xh, (uint2*)p_wh);
    cudaEventRecord(e0, 0);

    // 0b) remaining conversions + zeros on side stream, overlapping xz GEMM
    cudaStreamWaitEvent(s1, e0, 0);
    cvt_rest_k<<<(CVT_REST_TOTAL + 255)/256, 256, 0, s1>>>(
        (const float4*)W_out, (const float4*)Wx, (const float4*)Wx_b,
        (const float4*)Wdt, (const float4*)Wdt_b,
        (uint2*)p_wh, (float4*)p_dbc, (float4*)out);
    cudaEventRecord(e1, s1);

    // 1) xz = x @ W_in^T -> half
    gemm_f16w32<0,true><<<dim3(32,16,1), 512, SMEM128>>>(
        p_xh, CD, p_wh+OW_IN, CD, p_xzh, 2*CED, CD);

    // 2) conv + silu
    conv_silu_kernel<<<dim3(2*(CL/CONV_TCH), CB, 2), 256>>>(
        (const uint2*)p_xzh, (const float4*)conv_w, (const float4*)conv_b,
        (const float4*)conv_w_b, (const float4*)conv_b_b, (uint2*)p_xch);

    // join: Wx/Wdt halves + zeros ready
    cudaStreamWaitEvent(0, e1, 0);

    // 3) dbc = xc @ Wx^T (both dirs, split-K=8, fp32 atomics)
    gemm_f16<96,0,1,false><<<dim3(2,16,8), 192, SMEM96>>>(
        p_xch, CED, (size_t)BLED, p_wh+OWX_F, p_wh+OWX_B, CED,
        p_dbc, 96, (size_t)CML*96, CED, nullptr, nullptr);

    // 3b) dbc -> half
    f2h_k<<<(2*CML*96/2 + 255)/256, 256>>>((const float2*)p_dbc, (__half2*)p_dbch, 2*CML*96/2);

    // 4) delta = softplus(dbc[:, :64] @ Wdt^T + b_dt) -> half
    gemm_f16<128,1,2,true><<<dim3(16,16,2), 256, SMEM128>>>(
        p_dbch, 96, (size_t)CML*96, p_wh+OWDT_F, p_wh+OWDT_B, CRK,
        p_deltah, CED, (size_t)BLED, CRK, b_dt, b_dt_b);

    // 5) chunked scan: phase 1 (partial scans), phase 2 (fold + emit y)
    scan_p1<<<dim3(CED/128, CB, 2*NCH), 128>>>(
        p_deltah, p_xch, p_dbc, A_log, A_log_b, p_hmid, p_sd);
    scan_p2<<<dim3(CED/128, CB, 2*NCH), 128>>>(
        p_deltah, p_xch, p_dbc, p_xzh, A_log, A_log_b, Dp, Dp_b,
        p_hmid, p_sd, p_yh);

    // 6) combine -> half
    combine_kernel<<<(BLED/2)/256, 256>>>(
        (const __half2*)p_yh, (const __half2*)(p_yh + BLED), (__half2*)p_ych);

    // 7) out = yc @ W_out^T (split-K=2, fp32 atomics)
    gemm_f16w32<3,false><<<dim3(8,16,2), 512, SMEM128>>>(
        p_ych, CED, p_wh+OW_OUT, CED, out, CD, CED);
}